// round 1
// baseline (speedup 1.0000x reference)
#include <cuda_runtime.h>
#include <math.h>

#define NB 32
#define NV 2048
#define NEDGE 12288
#define NNZ (NEDGE + NV)   // 14336 (edges + self loops)

// ---------------- scratch (device globals; no allocation) ----------------
__device__ float g_bufA[(size_t)NB * NV * 512];   // 134 MB
__device__ float g_bufB[(size_t)NB * NV * 512];   // 134 MB
__device__ float g_s3a[NB * NV * 3];
__device__ float g_s3b[NB * NV * 3];
__device__ float g_s3c[NB * NV * 3];
__device__ float g_imgstage[NB * 512];
__device__ float g_imgterm[NB * 512];
__device__ float g_W34[512 * 512];
__device__ float g_W12c[3 * 512];
__device__ float g_W56[512 * 3];
__device__ float g_b1W2[512];
__device__ float g_b3W4[512];
__device__ float g_b5W6[3];
__device__ float g_s1[NV];
__device__ float g_s2[NV];
__device__ float g_dinv[NV];
__device__ float g_nrm[NNZ];
__device__ int   g_rowptr[NV + 1];
__device__ int   g_cols[NNZ];
__device__ int   g_counts[NV];
__device__ int   g_fill[NV];
__device__ float g_fch1[NB * 1024];
__device__ float g_fch2[NB * 1024];
__device__ float g_fcout[NB * 6144];

// ---------------- graph/CSR setup ----------------
__global__ void k_init() {
    int i = blockIdx.x * blockDim.x + threadIdx.x;
    if (i < NV) { g_counts[i] = 1; g_fill[i] = 0; }   // self loop pre-counted
}

__global__ void k_deg(const int* __restrict__ edge) {
    int e = blockIdx.x * blockDim.x + threadIdx.x;
    if (e < NEDGE) atomicAdd(&g_counts[edge[NEDGE + e]], 1);   // dst row
}

// single-block exclusive scan over NV=2048 counts -> row_ptr, plus dinv
__global__ void k_scan() {
    __shared__ int a[2048];
    __shared__ int p[1024];
    int t = threadIdx.x;
    int c0 = g_counts[2 * t], c1 = g_counts[2 * t + 1];
    a[2 * t] = c0; a[2 * t + 1] = c1;
    g_dinv[2 * t]     = rsqrtf((float)c0);
    g_dinv[2 * t + 1] = rsqrtf((float)c1);
    p[t] = c0 + c1;
    __syncthreads();
    for (int off = 1; off < 1024; off <<= 1) {
        int v = (t >= off) ? p[t - off] : 0;
        __syncthreads();
        p[t] += v;
        __syncthreads();
    }
    int base = p[t] - (c0 + c1);   // exclusive prefix of pair
    g_rowptr[2 * t] = base;
    g_rowptr[2 * t + 1] = base + c0;
    if (t == 1023) g_rowptr[2048] = p[1023];
}

__global__ void k_fill(const int* __restrict__ edge) {
    int i = blockIdx.x * blockDim.x + threadIdx.x;
    if (i < NEDGE) {
        int s = edge[i], d = edge[NEDGE + i];
        int pos = g_rowptr[d] + atomicAdd(&g_fill[d], 1);
        g_cols[pos] = s;
        g_nrm[pos] = g_dinv[s] * g_dinv[d];
    } else if (i < NNZ) {
        int v = i - NEDGE;
        int pos = g_rowptr[v] + atomicAdd(&g_fill[v], 1);
        g_cols[pos] = v;
        g_nrm[pos] = g_dinv[v] * g_dinv[v];
    }
}

__global__ void k_s1() {
    int v = blockIdx.x * blockDim.x + threadIdx.x;
    if (v >= NV) return;
    float s = 0.f;
    for (int j = g_rowptr[v]; j < g_rowptr[v + 1]; j++) s += g_nrm[j];
    g_s1[v] = s;
}
__global__ void k_s2() {
    int v = blockIdx.x * blockDim.x + threadIdx.x;
    if (v >= NV) return;
    float s = 0.f;
    for (int j = g_rowptr[v]; j < g_rowptr[v + 1]; j++) s += g_nrm[j] * g_s1[g_cols[j]];
    g_s2[v] = s;
}

// ---------------- generic small matmul: C[M,N] = A[M,K] @ B[K,N] ----------------
__global__ void k_smallmm(const float* __restrict__ A, const float* __restrict__ Bw,
                          float* __restrict__ C, int M, int K, int N, int strideA) {
    int i = blockIdx.x * blockDim.x + threadIdx.x;
    if (i >= M * N) return;
    int m = i / N, o = i - m * N;
    float acc = 0.f;
    const float* a = A + (size_t)m * strideA;
    for (int k = 0; k < K; k++) acc += a[k] * Bw[(size_t)k * N + o];
    C[i] = acc;
}

// ---------------- 128x128x8 SGEMM, 256 threads, 8x8/thread ----------------
__global__ void __launch_bounds__(256) sgemm128(const float* __restrict__ A,
                                                const float* __restrict__ Bw,
                                                float* __restrict__ C,
                                                int M, int N, int K) {
    __shared__ float As[8][128];
    __shared__ float Bs[8][128];
    int tid = threadIdx.x;
    int row0 = blockIdx.y * 128, col0 = blockIdx.x * 128;
    int aRow = tid >> 1, aCol = (tid & 1) * 4;
    int bRow = tid >> 5, bCol = (tid & 31) * 4;
    int tx = tid & 15, ty = tid >> 4;
    float acc[8][8];
#pragma unroll
    for (int i = 0; i < 8; i++)
#pragma unroll
        for (int j = 0; j < 8; j++) acc[i][j] = 0.f;

    const float* Ap = A + (size_t)(row0 + aRow) * K + aCol;
    const float* Bp = Bw + (size_t)bRow * N + col0 + bCol;

    for (int k0 = 0; k0 < K; k0 += 8) {
        float4 av = *(const float4*)Ap;  Ap += 8;
        float4 bv = *(const float4*)Bp;  Bp += (size_t)8 * N;
        As[aCol + 0][aRow] = av.x;
        As[aCol + 1][aRow] = av.y;
        As[aCol + 2][aRow] = av.z;
        As[aCol + 3][aRow] = av.w;
        *(float4*)&Bs[bRow][bCol] = bv;
        __syncthreads();
#pragma unroll
        for (int kk = 0; kk < 8; kk++) {
            float ar[8], br[8];
#pragma unroll
            for (int i = 0; i < 8; i++) ar[i] = As[kk][ty * 8 + i];
#pragma unroll
            for (int j = 0; j < 8; j++) br[j] = Bs[kk][tx * 8 + j];
#pragma unroll
            for (int i = 0; i < 8; i++)
#pragma unroll
                for (int j = 0; j < 8; j++) acc[i][j] = fmaf(ar[i], br[j], acc[i][j]);
        }
        __syncthreads();
    }
#pragma unroll
    for (int i = 0; i < 8; i++) {
        float* cp = C + (size_t)(row0 + ty * 8 + i) * N + col0 + tx * 8;
        float4 v0 = make_float4(acc[i][0], acc[i][1], acc[i][2], acc[i][3]);
        float4 v1 = make_float4(acc[i][4], acc[i][5], acc[i][6], acc[i][7]);
        *(float4*)cp = v0;
        *(float4*)(cp + 4) = v1;
    }
}

// ---------------- x2 assembly: A^2(verts)@W12c + s2*imgterm + s1*b1W2 + b2, relu ----------------
__global__ void k_x2(const float* __restrict__ b2) {
    int i = blockIdx.x * blockDim.x + threadIdx.x;       // over NB*NV*128 float4
    int og = i & 127;
    int bv = i >> 7;
    int v = bv & (NV - 1);
    int b = bv >> 11;
    float a0 = g_s3b[bv * 3 + 0], a1 = g_s3b[bv * 3 + 1], a2 = g_s3b[bv * 3 + 2];
    float4 w0 = ((const float4*)g_W12c)[0 * 128 + og];
    float4 w1 = ((const float4*)g_W12c)[1 * 128 + og];
    float4 w2 = ((const float4*)g_W12c)[2 * 128 + og];
    float4 it = ((const float4*)g_imgterm)[b * 128 + og];
    float4 bw = ((const float4*)g_b1W2)[og];
    float4 bb = ((const float4*)b2)[og];
    float s1v = g_s1[v], s2v = g_s2[v];
    float4 r;
    r.x = fmaxf(0.f, a0 * w0.x + a1 * w1.x + a2 * w2.x + s2v * it.x + s1v * bw.x + bb.x);
    r.y = fmaxf(0.f, a0 * w0.y + a1 * w1.y + a2 * w2.y + s2v * it.y + s1v * bw.y + bb.y);
    r.z = fmaxf(0.f, a0 * w0.z + a1 * w1.z + a2 * w2.z + s2v * it.z + s1v * bw.z + bb.z);
    r.w = fmaxf(0.f, a0 * w0.w + a1 * w1.w + a2 * w2.w + s2v * it.w + s1v * bw.w + bb.w);
    ((float4*)g_bufA)[(size_t)bv * 128 + og] = r;
}

// ---------------- aggregation, F=512 ----------------
__global__ void k_agg512(const float* __restrict__ in, float* __restrict__ out,
                         const float* __restrict__ biasA, const float* __restrict__ biasB,
                         int relu) {
    int v = blockIdx.x, b = blockIdx.y, t = threadIdx.x;   // t < 128 (float4 lanes)
    const float4* inb = (const float4*)(in + (size_t)b * NV * 512);
    float4 acc = make_float4(0.f, 0.f, 0.f, 0.f);
    int beg = g_rowptr[v], end = g_rowptr[v + 1];
    for (int j = beg; j < end; j++) {
        int s = g_cols[j];
        float w = g_nrm[j];
        float4 x = inb[(size_t)s * 128 + t];
        acc.x = fmaf(w, x.x, acc.x);
        acc.y = fmaf(w, x.y, acc.y);
        acc.z = fmaf(w, x.z, acc.z);
        acc.w = fmaf(w, x.w, acc.w);
    }
    if (biasA) {
        float s1v = g_s1[v];
        float4 ba = ((const float4*)biasA)[t];
        float4 bb = ((const float4*)biasB)[t];
        acc.x += s1v * ba.x + bb.x;
        acc.y += s1v * ba.y + bb.y;
        acc.z += s1v * ba.z + bb.z;
        acc.w += s1v * ba.w + bb.w;
    }
    if (relu) {
        acc.x = fmaxf(0.f, acc.x); acc.y = fmaxf(0.f, acc.y);
        acc.z = fmaxf(0.f, acc.z); acc.w = fmaxf(0.f, acc.w);
    }
    ((float4*)(out + (size_t)b * NV * 512))[(size_t)v * 128 + t] = acc;
}

// ---------------- aggregation, F=3 ----------------
__global__ void k_agg3(const float* __restrict__ in, float* __restrict__ out,
                       const float* __restrict__ biasA, const float* __restrict__ biasB,
                       int relu) {
    int i = blockIdx.x * blockDim.x + threadIdx.x;
    if (i >= NB * NV) return;
    int v = i & (NV - 1);
    int b = i >> 11;
    float a0 = 0.f, a1 = 0.f, a2 = 0.f;
    int beg = g_rowptr[v], end = g_rowptr[v + 1];
    const float* base = in + (size_t)b * NV * 3;
    for (int j = beg; j < end; j++) {
        int s = g_cols[j];
        float w = g_nrm[j];
        const float* p = base + s * 3;
        a0 = fmaf(w, p[0], a0);
        a1 = fmaf(w, p[1], a1);
        a2 = fmaf(w, p[2], a2);
    }
    if (biasA) {
        float s1v = g_s1[v];
        a0 += s1v * biasA[0] + biasB[0];
        a1 += s1v * biasA[1] + biasB[1];
        a2 += s1v * biasA[2] + biasB[2];
    }
    if (relu) { a0 = fmaxf(0.f, a0); a1 = fmaxf(0.f, a1); a2 = fmaxf(0.f, a2); }
    float* o = out + (size_t)i * 3;
    o[0] = a0; o[1] = a1; o[2] = a2;
}

// ---------------- [B*V,512] @ W56[512,3] (warp per row) ----------------
__global__ void k_w56(const float* __restrict__ in) {
    int gw = (blockIdx.x * blockDim.x + threadIdx.x) >> 5;
    int lane = threadIdx.x & 31;
    if (gw >= NB * NV) return;
    const float* row = in + (size_t)gw * 512;
    float a0 = 0.f, a1 = 0.f, a2 = 0.f;
    for (int k = lane; k < 512; k += 32) {
        float x = row[k];
        a0 = fmaf(x, g_W56[k * 3 + 0], a0);
        a1 = fmaf(x, g_W56[k * 3 + 1], a1);
        a2 = fmaf(x, g_W56[k * 3 + 2], a2);
    }
#pragma unroll
    for (int off = 16; off; off >>= 1) {
        a0 += __shfl_down_sync(0xffffffffu, a0, off);
        a1 += __shfl_down_sync(0xffffffffu, a1, off);
        a2 += __shfl_down_sync(0xffffffffu, a2, off);
    }
    if (lane == 0) {
        g_s3a[gw * 3 + 0] = a0;
        g_s3a[gw * 3 + 1] = a1;
        g_s3a[gw * 3 + 2] = a2;
    }
}

// ---------------- small-M FC GEMM: C[32,N] = A[32,K]@W + bias ----------------
__global__ void __launch_bounds__(256) fcgemm(const float* __restrict__ A,
                                              const float* __restrict__ W,
                                              const float* __restrict__ bias,
                                              float* __restrict__ C, int K, int N) {
    __shared__ float As[32][33];
    int tid = threadIdx.x;
    int o = blockIdx.x * 64 + (tid & 63);
    int bg = (tid >> 6) * 8;
    float acc[8];
#pragma unroll
    for (int r = 0; r < 8; r++) acc[r] = 0.f;
    for (int k0 = 0; k0 < K; k0 += 32) {
#pragma unroll
        for (int l = 0; l < 4; l++) {
            int idx = tid + 256 * l;
            int r = idx >> 5, kk = idx & 31;
            As[r][kk] = A[(size_t)r * K + k0 + kk];
        }
        __syncthreads();
#pragma unroll 8
        for (int kk = 0; kk < 32; kk++) {
            float w = W[(size_t)(k0 + kk) * N + o];
#pragma unroll
            for (int r = 0; r < 8; r++) acc[r] = fmaf(As[bg + r][kk], w, acc[r]);
        }
        __syncthreads();
    }
    float bo = bias[o];
#pragma unroll
    for (int r = 0; r < 8; r++) C[(size_t)(bg + r) * N + o] = acc[r] + bo;
}

// ---------------- final: out = verts + 0.1*tanh(fcout) ----------------
__global__ void k_final(const float* __restrict__ verts, float* __restrict__ out) {
    int i = blockIdx.x * blockDim.x + threadIdx.x;
    if (i >= NB * NV * 3) return;
    out[i] = verts[i] + 0.1f * tanhf(g_fcout[i]);
}

// ---------------- host launcher ----------------
extern "C" void kernel_launch(void* const* d_in, const int* in_sizes, int n_in,
                              void* d_out, int out_size) {
    const float* verts = (const float*)d_in[0];
    const float* img   = (const float*)d_in[1];
    const int*   edge  = (const int*)d_in[2];
    const float* W1 = (const float*)d_in[3];   const float* b1 = (const float*)d_in[4];
    const float* W2 = (const float*)d_in[5];   const float* b2 = (const float*)d_in[6];
    const float* W3 = (const float*)d_in[7];   const float* b3 = (const float*)d_in[8];
    const float* W4 = (const float*)d_in[9];   const float* b4 = (const float*)d_in[10];
    const float* W5 = (const float*)d_in[11];  const float* b5 = (const float*)d_in[12];
    const float* W6 = (const float*)d_in[13];  const float* b6 = (const float*)d_in[14];
    const float* fcW1 = (const float*)d_in[15]; const float* fcb1 = (const float*)d_in[16];
    const float* fcW2 = (const float*)d_in[17]; const float* fcb2 = (const float*)d_in[18];
    const float* fcW3 = (const float*)d_in[19]; const float* fcb3 = (const float*)d_in[20];
    float* out = (float*)d_out;

    float *bufA, *bufB, *s3a, *s3b, *s3c, *imgstage, *imgterm;
    float *W34, *W12c, *W56, *b1W2, *b3W4, *b5W6, *fch1, *fch2, *fcout;
    cudaGetSymbolAddress((void**)&bufA, g_bufA);
    cudaGetSymbolAddress((void**)&bufB, g_bufB);
    cudaGetSymbolAddress((void**)&s3a, g_s3a);
    cudaGetSymbolAddress((void**)&s3b, g_s3b);
    cudaGetSymbolAddress((void**)&s3c, g_s3c);
    cudaGetSymbolAddress((void**)&imgstage, g_imgstage);
    cudaGetSymbolAddress((void**)&imgterm, g_imgterm);
    cudaGetSymbolAddress((void**)&W34, g_W34);
    cudaGetSymbolAddress((void**)&W12c, g_W12c);
    cudaGetSymbolAddress((void**)&W56, g_W56);
    cudaGetSymbolAddress((void**)&b1W2, g_b1W2);
    cudaGetSymbolAddress((void**)&b3W4, g_b3W4);
    cudaGetSymbolAddress((void**)&b5W6, g_b5W6);
    cudaGetSymbolAddress((void**)&fch1, g_fch1);
    cudaGetSymbolAddress((void**)&fch2, g_fch2);
    cudaGetSymbolAddress((void**)&fcout, g_fcout);

    // --- graph/CSR + norm ---
    k_init<<<8, 256>>>();
    k_deg<<<48, 256>>>(edge);
    k_scan<<<1, 1024>>>();
    k_fill<<<56, 256>>>(edge);
    k_s1<<<8, 256>>>();
    k_s2<<<8, 256>>>();

    // --- fused weight precompute ---
    k_smallmm<<<6, 256>>>(W1, W2, W12c, 3, 512, 512, 512);          // W1[0:3]@W2
    k_smallmm<<<2, 256>>>(b1, W2, b1W2, 1, 512, 512, 512);
    k_smallmm<<<64, 256>>>(img, W1 + 3 * 512, imgstage, NB, 512, 512, 512);
    k_smallmm<<<64, 256>>>(imgstage, W2, imgterm, NB, 512, 512, 512);
    sgemm128<<<dim3(4, 4), 256>>>(W3, W4, W34, 512, 512, 512);       // W34 = W3@W4
    k_smallmm<<<2, 256>>>(b3, W4, b3W4, 1, 512, 512, 512);
    k_smallmm<<<6, 256>>>(W5, W6, W56, 512, 64, 3, 64);              // W56 = W5@W6
    k_smallmm<<<1, 256>>>(b5, W6, b5W6, 1, 64, 3, 64);

    // --- layers 1+2 fused: aggregate verts twice at F=3, then assemble x2 ---
    k_agg3<<<256, 256>>>(verts, s3a, NULL, NULL, 0);
    k_agg3<<<256, 256>>>(s3a, s3b, NULL, NULL, 0);
    k_x2<<<32768, 256>>>(b2);                                        // -> bufA (relu'd x2)

    // --- layers 3+4 fused: h = x2 @ W34, then A^2 + bias + relu ---
    sgemm128<<<dim3(4, 512), 256>>>(bufA, W34, bufB, NB * NV, 512, 512);
    k_agg512<<<dim3(NV, NB), 128>>>(bufB, bufA, NULL, NULL, 0);
    k_agg512<<<dim3(NV, NB), 128>>>(bufA, bufB, b3W4, b4, 1);        // -> bufB (relu'd x4)

    // --- layers 5+6 fused: v = x4 @ W56 (512->3), then A^2 + bias + relu ---
    k_w56<<<8192, 256>>>(bufB);                                      // -> s3a
    k_agg3<<<256, 256>>>(s3a, s3b, NULL, NULL, 0);
    k_agg3<<<256, 256>>>(s3b, s3c, b5W6, b6, 1);                     // -> s3c (x6, [32,6144])

    // --- FC head ---
    fcgemm<<<16, 256>>>(s3c, fcW1, fcb1, fch1, 6144, 1024);
    fcgemm<<<16, 256>>>(fch1, fcW2, fcb2, fch2, 1024, 1024);
    fcgemm<<<96, 256>>>(fch2, fcW3, fcb3, fcout, 1024, 6144);

    // --- output ---
    k_final<<<768, 256>>>(verts, out);
}

// round 4
// speedup vs baseline: 1.9631x; 1.9631x over previous
#include <cuda_runtime.h>
#include <cuda_bf16.h>
#include <cstdint>
#include <math.h>

#define NB 32
#define NV 2048
#define NEDGE 12288
#define NNZ (NEDGE + NV)   // 14336 (edges + self loops)

// ================= helpers (plain sm_103-safe: no tcgen05) =================
__device__ __forceinline__ uint32_t smem_to_u32(const void* smem_ptr) {
    uint32_t addr;
    asm("{ .reg .u64 tmp; cvta.to.shared.u64 tmp, %1; cvt.u32.u64 %0, tmp; }"
        : "=r"(addr) : "l"(smem_ptr));
    return addr;
}
#define SWZ(o) ((o) ^ (((o) >> 3) & 0x70))
#define CP_ASYNC16(dst, src) \
    asm volatile("cp.async.cg.shared.global [%0], [%1], 16;" :: "r"(dst), "l"(src))
#define CP_COMMIT asm volatile("cp.async.commit_group;" ::: "memory")
#define CP_WAIT0  asm volatile("cp.async.wait_group 0;" ::: "memory")
#define LDM4(r, addr) \
    asm volatile("ldmatrix.sync.aligned.m8n8.x4.shared.b16 {%0,%1,%2,%3}, [%4];" \
        : "=r"((r)[0]), "=r"((r)[1]), "=r"((r)[2]), "=r"((r)[3]) : "r"(addr))
#define MMA16816(d, a, b) \
    asm volatile("mma.sync.aligned.m16n8k16.row.col.f32.bf16.bf16.f32 " \
        "{%0,%1,%2,%3}, {%4,%5,%6,%7}, {%8,%9}, {%0,%1,%2,%3};" \
        : "+f"((d)[0]), "+f"((d)[1]), "+f"((d)[2]), "+f"((d)[3]) \
        : "r"((a)[0]), "r"((a)[1]), "r"((a)[2]), "r"((a)[3]), "r"((b)[0]), "r"((b)[1]))

// ---------------- scratch (device globals; no allocation) ----------------
__device__ float g_bufA[(size_t)NB * NV * 512];   // 134 MB: aliased as bf16 hi|lo planes for x2
__device__ float g_bufB[(size_t)NB * NV * 512];   // 134 MB: y = x2@W34 (fp32)
__device__ float g_s3a[NB * NV * 3];
__device__ float g_s3b[NB * NV * 3];
__device__ float g_s3c[NB * NV * 3];
__device__ float g_imgstage[NB * 512];
__device__ float g_imgterm[NB * 512];
__device__ float g_W34[512 * 512];
__device__ __nv_bfloat16 g_W34Thi[512 * 512];     // transposed [N,K] bf16 hi
__device__ __nv_bfloat16 g_W34Tlo[512 * 512];     // transposed [N,K] bf16 lo
__device__ float g_W12c[3 * 512];
__device__ float g_W56[512 * 3];
__device__ float g_b1W2[512];
__device__ float g_b3W4[512];
__device__ float g_b5W6[3];
__device__ float g_s1[NV];
__device__ float g_s2[NV];
__device__ float g_dinv[NV];
__device__ float g_nrm[NNZ];
__device__ int   g_rowptr[NV + 1];
__device__ int   g_cols[NNZ];
__device__ int   g_counts[NV];
__device__ int   g_fill[NV];
__device__ float g_fch1[NB * 1024];
__device__ float g_fch2[NB * 1024];
__device__ float g_fcout[NB * 6144];

// ---------------- graph/CSR setup ----------------
__global__ void k_init() {
    int i = blockIdx.x * blockDim.x + threadIdx.x;
    if (i < NV) { g_counts[i] = 1; g_fill[i] = 0; }
}
__global__ void k_deg(const int* __restrict__ edge) {
    int e = blockIdx.x * blockDim.x + threadIdx.x;
    if (e < NEDGE) atomicAdd(&g_counts[edge[NEDGE + e]], 1);
}
__global__ void k_scan() {
    __shared__ int p[1024];
    int t = threadIdx.x;
    int c0 = g_counts[2 * t], c1 = g_counts[2 * t + 1];
    g_dinv[2 * t]     = rsqrtf((float)c0);
    g_dinv[2 * t + 1] = rsqrtf((float)c1);
    p[t] = c0 + c1;
    __syncthreads();
    for (int off = 1; off < 1024; off <<= 1) {
        int v = (t >= off) ? p[t - off] : 0;
        __syncthreads();
        p[t] += v;
        __syncthreads();
    }
    int base = p[t] - (c0 + c1);
    g_rowptr[2 * t] = base;
    g_rowptr[2 * t + 1] = base + c0;
    if (t == 1023) g_rowptr[2048] = p[1023];
}
__global__ void k_fill(const int* __restrict__ edge) {
    int i = blockIdx.x * blockDim.x + threadIdx.x;
    if (i < NEDGE) {
        int s = edge[i], d = edge[NEDGE + i];
        int pos = g_rowptr[d] + atomicAdd(&g_fill[d], 1);
        g_cols[pos] = s;
        g_nrm[pos] = g_dinv[s] * g_dinv[d];
    } else if (i < NNZ) {
        int v = i - NEDGE;
        int pos = g_rowptr[v] + atomicAdd(&g_fill[v], 1);
        g_cols[pos] = v;
        g_nrm[pos] = g_dinv[v] * g_dinv[v];
    }
}
__global__ void k_s1() {
    int v = blockIdx.x * blockDim.x + threadIdx.x;
    if (v >= NV) return;
    float s = 0.f;
    for (int j = g_rowptr[v]; j < g_rowptr[v + 1]; j++) s += g_nrm[j];
    g_s1[v] = s;
}
__global__ void k_s2() {
    int v = blockIdx.x * blockDim.x + threadIdx.x;
    if (v >= NV) return;
    float s = 0.f;
    for (int j = g_rowptr[v]; j < g_rowptr[v + 1]; j++) s += g_nrm[j] * g_s1[g_cols[j]];
    g_s2[v] = s;
}

// ---------------- generic small matmul ----------------
__global__ void k_smallmm(const float* __restrict__ A, const float* __restrict__ Bw,
                          float* __restrict__ C, int M, int K, int N, int strideA) {
    int i = blockIdx.x * blockDim.x + threadIdx.x;
    if (i >= M * N) return;
    int m = i / N, o = i - m * N;
    float acc = 0.f;
    const float* a = A + (size_t)m * strideA;
    for (int k = 0; k < K; k++) acc += a[k] * Bw[(size_t)k * N + o];
    C[i] = acc;
}

// ---------------- 64x64 fp32 SGEMM for W34 precompute ----------------
__global__ void __launch_bounds__(256) sgemm64(const float* __restrict__ A,
                                               const float* __restrict__ Bw,
                                               float* __restrict__ C,
                                               int M, int N, int K) {
    __shared__ float As[16][64];
    __shared__ float Bs[16][68];
    int tid = threadIdx.x;
    int row0 = blockIdx.y * 64, col0 = blockIdx.x * 64;
    int aRow = tid >> 2, aCol = (tid & 3) * 4;
    int bRow = tid >> 4, bCol = (tid & 15) * 4;
    int tx = tid & 15, ty = tid >> 4;
    float acc[4][4];
#pragma unroll
    for (int i = 0; i < 4; i++)
#pragma unroll
        for (int j = 0; j < 4; j++) acc[i][j] = 0.f;
    for (int k0 = 0; k0 < K; k0 += 16) {
        float4 av = *(const float4*)&A[(size_t)(row0 + aRow) * K + k0 + aCol];
        float4 bv = *(const float4*)&Bw[(size_t)(k0 + bRow) * N + col0 + bCol];
        As[aCol + 0][aRow] = av.x;
        As[aCol + 1][aRow] = av.y;
        As[aCol + 2][aRow] = av.z;
        As[aCol + 3][aRow] = av.w;
        Bs[bRow][bCol + 0] = bv.x;
        Bs[bRow][bCol + 1] = bv.y;
        Bs[bRow][bCol + 2] = bv.z;
        Bs[bRow][bCol + 3] = bv.w;
        __syncthreads();
#pragma unroll
        for (int kk = 0; kk < 16; kk++) {
            float ar[4], br[4];
#pragma unroll
            for (int i = 0; i < 4; i++) ar[i] = As[kk][ty * 4 + i];
#pragma unroll
            for (int j = 0; j < 4; j++) br[j] = Bs[kk][tx * 4 + j];
#pragma unroll
            for (int i = 0; i < 4; i++)
#pragma unroll
                for (int j = 0; j < 4; j++) acc[i][j] = fmaf(ar[i], br[j], acc[i][j]);
        }
        __syncthreads();
    }
#pragma unroll
    for (int i = 0; i < 4; i++) {
        float4 v = make_float4(acc[i][0], acc[i][1], acc[i][2], acc[i][3]);
        *(float4*)&C[(size_t)(row0 + ty * 4 + i) * N + col0 + tx * 4] = v;
    }
}

// transpose W34 [K,N] -> [N,K] and split to bf16 hi/lo
__global__ void k_splitT() {
    int i = blockIdx.x * blockDim.x + threadIdx.x;   // 512*512
    int n = i >> 9, k = i & 511;
    float w = g_W34[(size_t)k * 512 + n];
    __nv_bfloat16 h = __float2bfloat16(w);
    g_W34Thi[i] = h;
    g_W34Tlo[i] = __float2bfloat16(w - __bfloat162float(h));
}

// ---------------- x2 assembly -> bf16 hi/lo planes ----------------
__global__ void k_x2(const float* __restrict__ b2,
                     __nv_bfloat16* __restrict__ ahi, __nv_bfloat16* __restrict__ alo) {
    int i = blockIdx.x * blockDim.x + threadIdx.x;       // over NB*NV*128 float4
    int og = i & 127;
    int bv = i >> 7;
    int v = bv & (NV - 1);
    int b = bv >> 11;
    float a0 = g_s3b[bv * 3 + 0], a1 = g_s3b[bv * 3 + 1], a2 = g_s3b[bv * 3 + 2];
    float4 w0 = ((const float4*)g_W12c)[0 * 128 + og];
    float4 w1 = ((const float4*)g_W12c)[1 * 128 + og];
    float4 w2 = ((const float4*)g_W12c)[2 * 128 + og];
    float4 it = ((const float4*)g_imgterm)[b * 128 + og];
    float4 bw = ((const float4*)g_b1W2)[og];
    float4 bb = ((const float4*)b2)[og];
    float s1v = g_s1[v], s2v = g_s2[v];
    float r[4];
    r[0] = fmaxf(0.f, a0 * w0.x + a1 * w1.x + a2 * w2.x + s2v * it.x + s1v * bw.x + bb.x);
    r[1] = fmaxf(0.f, a0 * w0.y + a1 * w1.y + a2 * w2.y + s2v * it.y + s1v * bw.y + bb.y);
    r[2] = fmaxf(0.f, a0 * w0.z + a1 * w1.z + a2 * w2.z + s2v * it.z + s1v * bw.z + bb.z);
    r[3] = fmaxf(0.f, a0 * w0.w + a1 * w1.w + a2 * w2.w + s2v * it.w + s1v * bw.w + bb.w);
    ushort4 hv, lv;
    unsigned short* hp = &hv.x;
    unsigned short* lp = &lv.x;
#pragma unroll
    for (int q = 0; q < 4; q++) {
        __nv_bfloat16 h = __float2bfloat16(r[q]);
        __nv_bfloat16 l = __float2bfloat16(r[q] - __bfloat162float(h));
        hp[q] = *(unsigned short*)&h;
        lp[q] = *(unsigned short*)&l;
    }
    ((ushort4*)ahi)[(size_t)bv * 128 + og] = hv;
    ((ushort4*)alo)[(size_t)bv * 128 + og] = lv;
}

// ---------------- mma.sync bf16 split-precision GEMM: C[65536,512] = A @ W34 ----------------
// A hi/lo bf16 [M,512] row-major; B = W34^T hi/lo bf16 [512,512] (rows=n, cols=k) -> .col
// CTA 128x128, 8 warps (warp tile 32x64), K-chunk 32, double-buffered cp.async.
// Stage layout (32 KB): Ah@0, Al@8192, Bh@16384, Bl@24576. 2 stages = 64 KB dynamic.
__global__ void __launch_bounds__(256, 2) gemm_mma(
    const uint4* __restrict__ Ahi, const uint4* __restrict__ Alo,
    const uint4* __restrict__ Bhi, const uint4* __restrict__ Blo,
    float* __restrict__ C) {
    extern __shared__ char smem[];
    uint32_t sb = smem_to_u32(smem);
    int tid = threadIdx.x, lane = tid & 31, wid = tid >> 5;
    int wr = wid & 3, wc = wid >> 2;                 // warp row (m), warp col (n)
    int row0 = blockIdx.y << 7, col0 = blockIdx.x << 7;

    // chunk loader: 4 tiles of 128 rows x 32 bf16 (64B rows), swizzled
    auto load_chunk = [&](int kc, int stage) {
        uint32_t st = sb + stage * 32768;
#pragma unroll
        for (int i = tid; i < 512; i += 256) {
            int r = i >> 2, c = i & 3;
            uint32_t soff = SWZ(r * 64 + c * 16);
            size_t ga = (size_t)(row0 + r) * 64 + kc * 4 + c;
            size_t gb = (size_t)(col0 + r) * 64 + kc * 4 + c;
            CP_ASYNC16(st + soff,         (const void*)(Ahi + ga));
            CP_ASYNC16(st + 8192 + soff,  (const void*)(Alo + ga));
            CP_ASYNC16(st + 16384 + soff, (const void*)(Bhi + gb));
            CP_ASYNC16(st + 24576 + soff, (const void*)(Blo + gb));
        }
    };

    load_chunk(0, 0);
    CP_COMMIT;
    CP_WAIT0;
    __syncthreads();

    float acc[2][8][4];
#pragma unroll
    for (int mt = 0; mt < 2; mt++)
#pragma unroll
        for (int nt = 0; nt < 8; nt++)
#pragma unroll
            for (int q = 0; q < 4; q++) acc[mt][nt][q] = 0.f;

    for (int kc = 0; kc < 16; kc++) {
        if (kc < 15) { load_chunk(kc + 1, (kc + 1) & 1); CP_COMMIT; }
        uint32_t base = sb + (kc & 1) * 32768;
#pragma unroll
        for (int ks = 0; ks < 2; ks++) {
            uint32_t ah[2][4], al[2][4];
#pragma unroll
            for (int mt = 0; mt < 2; mt++) {
                int r = wr * 32 + mt * 16 + (lane & 15);
                uint32_t off = SWZ(r * 64 + ks * 32 + ((lane >> 4) << 4));
                LDM4(ah[mt], base + off);
                LDM4(al[mt], base + 8192 + off);
            }
#pragma unroll
            for (int nt2 = 0; nt2 < 4; nt2++) {
                int nrow = wc * 64 + nt2 * 16 + (lane & 7) + ((lane >> 4) << 3);
                uint32_t off = SWZ(nrow * 64 + ks * 32 + (((lane >> 3) & 1) << 4));
                uint32_t bhf[4], blf[4];
                LDM4(bhf, base + 16384 + off);
                LDM4(blf, base + 24576 + off);
#pragma unroll
                for (int h = 0; h < 2; h++) {
                    uint32_t bh2[2] = { bhf[2 * h], bhf[2 * h + 1] };
                    uint32_t bl2[2] = { blf[2 * h], blf[2 * h + 1] };
                    int nt = 2 * nt2 + h;
#pragma unroll
                    for (int mt = 0; mt < 2; mt++) {
                        MMA16816(acc[mt][nt], ah[mt], bh2);
                        MMA16816(acc[mt][nt], al[mt], bh2);
                        MMA16816(acc[mt][nt], ah[mt], bl2);
                    }
                }
            }
        }
        if (kc < 15) CP_WAIT0;
        __syncthreads();
    }

    // epilogue: C row = row0 + wr*32 + mt*16 + lane/4 (+8), col = col0 + wc*64 + nt*8 + 2*(lane%4)
#pragma unroll
    for (int mt = 0; mt < 2; mt++) {
        int row = row0 + wr * 32 + mt * 16 + (lane >> 2);
#pragma unroll
        for (int nt = 0; nt < 8; nt++) {
            int col = col0 + wc * 64 + nt * 8 + ((lane & 3) << 1);
            *(float2*)&C[(size_t)row * 512 + col] = make_float2(acc[mt][nt][0], acc[mt][nt][1]);
            *(float2*)&C[(size_t)(row + 8) * 512 + col] = make_float2(acc[mt][nt][2], acc[mt][nt][3]);
        }
    }
}

// ---------------- aggregation, F=512 (plain) ----------------
__global__ void k_agg512(const float* __restrict__ in, float* __restrict__ out) {
    int v = blockIdx.x, b = blockIdx.y, t = threadIdx.x;   // t < 128
    const float4* inb = (const float4*)(in + (size_t)b * NV * 512);
    float4 acc = make_float4(0.f, 0.f, 0.f, 0.f);
    int beg = g_rowptr[v], end = g_rowptr[v + 1];
    for (int j = beg; j < end; j++) {
        int s = g_cols[j];
        float w = g_nrm[j];
        float4 x = inb[(size_t)s * 128 + t];
        acc.x = fmaf(w, x.x, acc.x);
        acc.y = fmaf(w, x.y, acc.y);
        acc.z = fmaf(w, x.z, acc.z);
        acc.w = fmaf(w, x.w, acc.w);
    }
    ((float4*)(out + (size_t)b * NV * 512))[(size_t)v * 128 + t] = acc;
}

// ---------------- second F=512 aggregation fused with bias+relu+W56 projection ----------------
__global__ void k_agg512_w56(const float* __restrict__ in, const float* __restrict__ b4) {
    int v = blockIdx.x, b = blockIdx.y, t = threadIdx.x;   // t < 128
    const float4* inb = (const float4*)(in + (size_t)b * NV * 512);
    float4 acc = make_float4(0.f, 0.f, 0.f, 0.f);
    int beg = g_rowptr[v], end = g_rowptr[v + 1];
    for (int j = beg; j < end; j++) {
        int s = g_cols[j];
        float w = g_nrm[j];
        float4 x = inb[(size_t)s * 128 + t];
        acc.x = fmaf(w, x.x, acc.x);
        acc.y = fmaf(w, x.y, acc.y);
        acc.z = fmaf(w, x.z, acc.z);
        acc.w = fmaf(w, x.w, acc.w);
    }
    float s1v = g_s1[v];
    float4 ba = ((const float4*)g_b3W4)[t];
    float4 bb = ((const float4*)b4)[t];
    acc.x = fmaxf(0.f, acc.x + s1v * ba.x + bb.x);
    acc.y = fmaxf(0.f, acc.y + s1v * ba.y + bb.y);
    acc.z = fmaxf(0.f, acc.z + s1v * ba.z + bb.z);
    acc.w = fmaxf(0.f, acc.w + s1v * ba.w + bb.w);
    // project onto W56 (512 -> 3): thread t owns features 4t..4t+3
    float p0 = acc.x * g_W56[(4 * t + 0) * 3 + 0] + acc.y * g_W56[(4 * t + 1) * 3 + 0]
             + acc.z * g_W56[(4 * t + 2) * 3 + 0] + acc.w * g_W56[(4 * t + 3) * 3 + 0];
    float p1 = acc.x * g_W56[(4 * t + 0) * 3 + 1] + acc.y * g_W56[(4 * t + 1) * 3 + 1]
             + acc.z * g_W56[(4 * t + 2) * 3 + 1] + acc.w * g_W56[(4 * t + 3) * 3 + 1];
    float p2 = acc.x * g_W56[(4 * t + 0) * 3 + 2] + acc.y * g_W56[(4 * t + 1) * 3 + 2]
             + acc.z * g_W56[(4 * t + 2) * 3 + 2] + acc.w * g_W56[(4 * t + 3) * 3 + 2];
#pragma unroll
    for (int off = 16; off; off >>= 1) {
        p0 += __shfl_down_sync(0xffffffffu, p0, off);
        p1 += __shfl_down_sync(0xffffffffu, p1, off);
        p2 += __shfl_down_sync(0xffffffffu, p2, off);
    }
    __shared__ float red[4][3];
    if ((t & 31) == 0) {
        red[t >> 5][0] = p0; red[t >> 5][1] = p1; red[t >> 5][2] = p2;
    }
    __syncthreads();
    if (t == 0) {
        float* o = g_s3a + ((size_t)b * NV + v) * 3;
        o[0] = red[0][0] + red[1][0] + red[2][0] + red[3][0];
        o[1] = red[0][1] + red[1][1] + red[2][1] + red[3][1];
        o[2] = red[0][2] + red[1][2] + red[2][2] + red[3][2];
    }
}

// ---------------- aggregation, F=3 ----------------
__global__ void k_agg3(const float* __restrict__ in, float* __restrict__ out,
                       const float* __restrict__ biasA, const float* __restrict__ biasB,
                       int relu) {
    int i = blockIdx.x * blockDim.x + threadIdx.x;
    if (i >= NB * NV) return;
    int v = i & (NV - 1);
    int b = i >> 11;
    float a0 = 0.f, a1 = 0.f, a2 = 0.f;
    int beg = g_rowptr[v], end = g_rowptr[v + 1];
    const float* base = in + (size_t)b * NV * 3;
    for (int j = beg; j < end; j++) {
        int s = g_cols[j];
        float w = g_nrm[j];
        const float* p = base + s * 3;
        a0 = fmaf(w, p[0], a0);
        a1 = fmaf(w, p[1], a1);
        a2 = fmaf(w, p[2], a2);
    }
    if (biasA) {
        float s1v = g_s1[v];
        a0 += s1v * biasA[0] + biasB[0];
        a1 += s1v * biasA[1] + biasB[1];
        a2 += s1v * biasA[2] + biasB[2];
    }
    if (relu) { a0 = fmaxf(0.f, a0); a1 = fmaxf(0.f, a1); a2 = fmaxf(0.f, a2); }
    float* o = out + (size_t)i * 3;
    o[0] = a0; o[1] = a1; o[2] = a2;
}

// ---------------- small-M FC GEMM ----------------
__global__ void __launch_bounds__(256) fcgemm(const float* __restrict__ A,
                                              const float* __restrict__ W,
                                              const float* __restrict__ bias,
                                              float* __restrict__ C, int K, int N) {
    __shared__ float As[32][33];
    int tid = threadIdx.x;
    int o = blockIdx.x * 64 + (tid & 63);
    int bg = (tid >> 6) * 8;
    float acc[8];
#pragma unroll
    for (int r = 0; r < 8; r++) acc[r] = 0.f;
    for (int k0 = 0; k0 < K; k0 += 32) {
#pragma unroll
        for (int l = 0; l < 4; l++) {
            int idx = tid + 256 * l;
            int r = idx >> 5, kk = idx & 31;
            As[r][kk] = A[(size_t)r * K + k0 + kk];
        }
        __syncthreads();
#pragma unroll 8
        for (int kk = 0; kk < 32; kk++) {
            float w = W[(size_t)(k0 + kk) * N + o];
#pragma unroll
            for (int r = 0; r < 8; r++) acc[r] = fmaf(As[bg + r][kk], w, acc[r]);
        }
        __syncthreads();
    }
    float bo = bias[o];
#pragma unroll
    for (int r = 0; r < 8; r++) C[(size_t)(bg + r) * N + o] = acc[r] + bo;
}

// ---------------- final: out = verts + 0.1*tanh(fcout) ----------------
__global__ void k_final(const float* __restrict__ verts, float* __restrict__ out) {
    int i = blockIdx.x * blockDim.x + threadIdx.x;
    if (i >= NB * NV * 3) return;
    out[i] = verts[i] + 0.1f * tanhf(g_fcout[i]);
}

// ---------------- host launcher ----------------
extern "C" void kernel_launch(void* const* d_in, const int* in_sizes, int n_in,
                              void* d_out, int out_size) {
    const float* verts = (const float*)d_in[0];
    const float* img   = (const float*)d_in[1];
    const int*   edge  = (const int*)d_in[2];
    const float* W1 = (const float*)d_in[3];   const float* b1 = (const float*)d_in[4];
    const float* W2 = (const float*)d_in[5];   const float* b2 = (const float*)d_in[6];
    const float* W3 = (const float*)d_in[7];   const float* b3 = (const float*)d_in[8];
    const float* W4 = (const float*)d_in[9];   const float* b4 = (const float*)d_in[10];
    const float* W5 = (const float*)d_in[11];  const float* b5 = (const float*)d_in[12];
    const float* W6 = (const float*)d_in[13];  const float* b6 = (const float*)d_in[14];
    const float* fcW1 = (const float*)d_in[15]; const float* fcb1 = (const float*)d_in[16];
    const float* fcW2 = (const float*)d_in[17]; const float* fcb2 = (const float*)d_in[18];
    const float* fcW3 = (const float*)d_in[19]; const float* fcb3 = (const float*)d_in[20];
    float* out = (float*)d_out;

    float *bufA, *bufB, *s3a, *s3b, *s3c, *imgstage, *imgterm;
    float *W34, *W12c, *W56, *b1W2, *b3W4, *b5W6, *fch1, *fch2, *fcout;
    __nv_bfloat16 *w34thi, *w34tlo;
    cudaGetSymbolAddress((void**)&bufA, g_bufA);
    cudaGetSymbolAddress((void**)&bufB, g_bufB);
    cudaGetSymbolAddress((void**)&s3a, g_s3a);
    cudaGetSymbolAddress((void**)&s3b, g_s3b);
    cudaGetSymbolAddress((void**)&s3c, g_s3c);
    cudaGetSymbolAddress((void**)&imgstage, g_imgstage);
    cudaGetSymbolAddress((void**)&imgterm, g_imgterm);
    cudaGetSymbolAddress((void**)&W34, g_W34);
    cudaGetSymbolAddress((void**)&w34thi, g_W34Thi);
    cudaGetSymbolAddress((void**)&w34tlo, g_W34Tlo);
    cudaGetSymbolAddress((void**)&W12c, g_W12c);
    cudaGetSymbolAddress((void**)&W56, g_W56);
    cudaGetSymbolAddress((void**)&b1W2, g_b1W2);
    cudaGetSymbolAddress((void**)&b3W4, g_b3W4);
    cudaGetSymbolAddress((void**)&b5W6, g_b5W6);
    cudaGetSymbolAddress((void**)&fch1, g_fch1);
    cudaGetSymbolAddress((void**)&fch2, g_fch2);
    cudaGetSymbolAddress((void**)&fcout, g_fcout);

    // bf16 hi/lo planes of x2 alias bufA (2 x 67MB = 134MB)
    __nv_bfloat16* ahi = (__nv_bfloat16*)bufA;
    __nv_bfloat16* alo = ahi + (size_t)NB * NV * 512;

    cudaFuncSetAttribute(gemm_mma, cudaFuncAttributeMaxDynamicSharedMemorySize, 65536);

    // --- graph/CSR + norm ---
    k_init<<<8, 256>>>();
    k_deg<<<48, 256>>>(edge);
    k_scan<<<1, 1024>>>();
    k_fill<<<56, 256>>>(edge);
    k_s1<<<8, 256>>>();
    k_s2<<<8, 256>>>();

    // --- fused weight precompute ---
    k_smallmm<<<6, 256>>>(W1, W2, W12c, 3, 512, 512, 512);
    k_smallmm<<<2, 256>>>(b1, W2, b1W2, 1, 512, 512, 512);
    k_smallmm<<<64, 256>>>(img, W1 + 3 * 512, imgstage, NB, 512, 512, 512);
    k_smallmm<<<64, 256>>>(imgstage, W2, imgterm, NB, 512, 512, 512);
    sgemm64<<<dim3(8, 8), 256>>>(W3, W4, W34, 512, 512, 512);
    k_splitT<<<1024, 256>>>();
    k_smallmm<<<2, 256>>>(b3, W4, b3W4, 1, 512, 512, 512);
    k_smallmm<<<6, 256>>>(W5, W6, W56, 512, 64, 3, 64);
    k_smallmm<<<1, 256>>>(b5, W6, b5W6, 1, 64, 3, 64);

    // --- layers 1+2 fused ---
    k_agg3<<<256, 256>>>(verts, s3a, NULL, NULL, 0);
    k_agg3<<<256, 256>>>(s3a, s3b, NULL, NULL, 0);
    k_x2<<<32768, 256>>>(b2, ahi, alo);

    // --- layers 3+4 fused: y = x2 @ W34 (mma.sync), then A^2 + bias + relu (+W56 proj) ---
    gemm_mma<<<dim3(4, 512), 256, 65536>>>(
        (const uint4*)ahi, (const uint4*)alo,
        (const uint4*)w34thi, (const uint4*)w34tlo, bufB);
    k_agg512<<<dim3(NV, NB), 128>>>(bufB, bufA);
    k_agg512_w56<<<dim3(NV, NB), 128>>>(bufA, b4);     // -> s3a (already projected by W56)

    // --- layers 5+6 remainder: A^2 on F=3 + bias + relu ---
    k_agg3<<<256, 256>>>(s3a, s3b, NULL, NULL, 0);
    k_agg3<<<256, 256>>>(s3b, s3c, b5W6, b6, 1);       // -> s3c ([32, 6144])

    // --- FC head ---
    fcgemm<<<16, 256>>>(s3c, fcW1, fcb1, fch1, 6144, 1024);
    fcgemm<<<16, 256>>>(fch1, fcW2, fcb2, fch2, 1024, 1024);
    fcgemm<<<96, 256>>>(fch2, fcW3, fcb3, fcout, 1024, 6144);

    // --- output ---
    k_final<<<768, 256>>>(verts, out);
}

// round 6
// speedup vs baseline: 3.4743x; 1.7698x over previous
#include <cuda_runtime.h>
#include <cuda_bf16.h>
#include <cstdint>
#include <math.h>

#define NB 32
#define NV 2048
#define NEDGE 12288
#define NNZ (NEDGE + NV)   // 14336 (edges + self loops)

// ================= helpers (plain sm_103-safe) =================
__device__ __forceinline__ uint32_t smem_to_u32(const void* smem_ptr) {
    uint32_t addr;
    asm("{ .reg .u64 tmp; cvta.to.shared.u64 tmp, %1; cvt.u32.u64 %0, tmp; }"
        : "=r"(addr) : "l"(smem_ptr));
    return addr;
}
#define SWZ(o) ((o) ^ (((o) >> 3) & 0x70))
#define CP_ASYNC16(dst, src) \
    asm volatile("cp.async.cg.shared.global [%0], [%1], 16;" :: "r"(dst), "l"(src))
#define CP_COMMIT asm volatile("cp.async.commit_group;" ::: "memory")
#define CP_WAIT0  asm volatile("cp.async.wait_group 0;" ::: "memory")
#define LDM4(r, addr) \
    asm volatile("ldmatrix.sync.aligned.m8n8.x4.shared.b16 {%0,%1,%2,%3}, [%4];" \
        : "=r"((r)[0]), "=r"((r)[1]), "=r"((r)[2]), "=r"((r)[3]) : "r"(addr))
#define MMA16816(d, a, b) \
    asm volatile("mma.sync.aligned.m16n8k16.row.col.f32.bf16.bf16.f32 " \
        "{%0,%1,%2,%3}, {%4,%5,%6,%7}, {%8,%9}, {%0,%1,%2,%3};" \
        : "+f"((d)[0]), "+f"((d)[1]), "+f"((d)[2]), "+f"((d)[3]) \
        : "r"((a)[0]), "r"((a)[1]), "r"((a)[2]), "r"((a)[3]), "r"((b)[0]), "r"((b)[1]))

// ---------------- scratch (device globals; no allocation) ----------------
__device__ float g_bufA[(size_t)NB * NV * 512];   // reused: x2 bf16 plane, then agg1 bf16 out
__device__ float g_bufB[(size_t)NB * NV * 512];   // reused: y = x2@W34 in bf16
__device__ float g_s3a[NB * NV * 3];
__device__ float g_s3b[NB * NV * 3];
__device__ float g_s3c[NB * NV * 3];
__device__ float g_imgstage[NB * 512];
__device__ float g_imgterm[NB * 512];
__device__ float g_W34[512 * 512];
__device__ __nv_bfloat16 g_W34T[512 * 512];       // transposed [N,K] bf16
__device__ float g_W12c[3 * 512];
__device__ float g_W56[512 * 3];
__device__ float g_b1W2[512];
__device__ float g_b3W4[512];
__device__ float g_b5W6[3];
__device__ float g_s1[NV];
__device__ float g_s2[NV];
__device__ float g_dinv[NV];
__device__ float g_nrm[NNZ];
__device__ int   g_rowptr[NV + 1];
__device__ int   g_cols[NNZ];
__device__ int   g_counts[NV];
__device__ int   g_fill[NV];
__device__ float g_fch1[NB * 1024];
__device__ float g_fch2[NB * 1024];
__device__ float g_fcout[NB * 6144];

// ---------------- graph/CSR setup ----------------
__global__ void k_init() {
    int i = blockIdx.x * blockDim.x + threadIdx.x;
    if (i < NV) { g_counts[i] = 1; g_fill[i] = 0; }
}
__global__ void k_deg(const int* __restrict__ edge) {
    int e = blockIdx.x * blockDim.x + threadIdx.x;
    if (e < NEDGE) atomicAdd(&g_counts[edge[NEDGE + e]], 1);
}
__global__ void k_scan() {
    __shared__ int p[1024];
    int t = threadIdx.x;
    int c0 = g_counts[2 * t], c1 = g_counts[2 * t + 1];
    g_dinv[2 * t]     = rsqrtf((float)c0);
    g_dinv[2 * t + 1] = rsqrtf((float)c1);
    p[t] = c0 + c1;
    __syncthreads();
    for (int off = 1; off < 1024; off <<= 1) {
        int v = (t >= off) ? p[t - off] : 0;
        __syncthreads();
        p[t] += v;
        __syncthreads();
    }
    int base = p[t] - (c0 + c1);
    g_rowptr[2 * t] = base;
    g_rowptr[2 * t + 1] = base + c0;
    if (t == 1023) g_rowptr[2048] = p[1023];
}
__global__ void k_fill(const int* __restrict__ edge) {
    int i = blockIdx.x * blockDim.x + threadIdx.x;
    if (i < NEDGE) {
        int s = edge[i], d = edge[NEDGE + i];
        int pos = g_rowptr[d] + atomicAdd(&g_fill[d], 1);
        g_cols[pos] = s;
        g_nrm[pos] = g_dinv[s] * g_dinv[d];
    } else if (i < NNZ) {
        int v = i - NEDGE;
        int pos = g_rowptr[v] + atomicAdd(&g_fill[v], 1);
        g_cols[pos] = v;
        g_nrm[pos] = g_dinv[v] * g_dinv[v];
    }
}
__global__ void k_s1() {
    int v = blockIdx.x * blockDim.x + threadIdx.x;
    if (v >= NV) return;
    float s = 0.f;
    for (int j = g_rowptr[v]; j < g_rowptr[v + 1]; j++) s += g_nrm[j];
    g_s1[v] = s;
}
__global__ void k_s2() {
    int v = blockIdx.x * blockDim.x + threadIdx.x;
    if (v >= NV) return;
    float s = 0.f;
    for (int j = g_rowptr[v]; j < g_rowptr[v + 1]; j++) s += g_nrm[j] * g_s1[g_cols[j]];
    g_s2[v] = s;
}

// ---------------- generic small matmul ----------------
__global__ void k_smallmm(const float* __restrict__ A, const float* __restrict__ Bw,
                          float* __restrict__ C, int M, int K, int N, int strideA) {
    int i = blockIdx.x * blockDim.x + threadIdx.x;
    if (i >= M * N) return;
    int m = i / N, o = i - m * N;
    float acc = 0.f;
    const float* a = A + (size_t)m * strideA;
    for (int k = 0; k < K; k++) acc += a[k] * Bw[(size_t)k * N + o];
    C[i] = acc;
}

// ---------------- 64x64 fp32 SGEMM for W34 precompute ----------------
__global__ void __launch_bounds__(256) sgemm64(const float* __restrict__ A,
                                               const float* __restrict__ Bw,
                                               float* __restrict__ C,
                                               int M, int N, int K) {
    __shared__ float As[16][64];
    __shared__ float Bs[16][68];
    int tid = threadIdx.x;
    int row0 = blockIdx.y * 64, col0 = blockIdx.x * 64;
    int aRow = tid >> 2, aCol = (tid & 3) * 4;
    int bRow = tid >> 4, bCol = (tid & 15) * 4;
    int tx = tid & 15, ty = tid >> 4;
    float acc[4][4];
#pragma unroll
    for (int i = 0; i < 4; i++)
#pragma unroll
        for (int j = 0; j < 4; j++) acc[i][j] = 0.f;
    for (int k0 = 0; k0 < K; k0 += 16) {
        float4 av = *(const float4*)&A[(size_t)(row0 + aRow) * K + k0 + aCol];
        float4 bv = *(const float4*)&Bw[(size_t)(k0 + bRow) * N + col0 + bCol];
        As[aCol + 0][aRow] = av.x;
        As[aCol + 1][aRow] = av.y;
        As[aCol + 2][aRow] = av.z;
        As[aCol + 3][aRow] = av.w;
        Bs[bRow][bCol + 0] = bv.x;
        Bs[bRow][bCol + 1] = bv.y;
        Bs[bRow][bCol + 2] = bv.z;
        Bs[bRow][bCol + 3] = bv.w;
        __syncthreads();
#pragma unroll
        for (int kk = 0; kk < 16; kk++) {
            float ar[4], br[4];
#pragma unroll
            for (int i = 0; i < 4; i++) ar[i] = As[kk][ty * 4 + i];
#pragma unroll
            for (int j = 0; j < 4; j++) br[j] = Bs[kk][tx * 4 + j];
#pragma unroll
            for (int i = 0; i < 4; i++)
#pragma unroll
                for (int j = 0; j < 4; j++) acc[i][j] = fmaf(ar[i], br[j], acc[i][j]);
        }
        __syncthreads();
    }
#pragma unroll
    for (int i = 0; i < 4; i++) {
        float4 v = make_float4(acc[i][0], acc[i][1], acc[i][2], acc[i][3]);
        *(float4*)&C[(size_t)(row0 + ty * 4 + i) * N + col0 + tx * 4] = v;
    }
}

// transpose W34 [K,N] -> [N,K] bf16
__global__ void k_splitT() {
    int i = blockIdx.x * blockDim.x + threadIdx.x;   // 512*512
    int n = i >> 9, k = i & 511;
    g_W34T[i] = __float2bfloat16(g_W34[(size_t)k * 512 + n]);
}

// ---------------- x2 assembly -> bf16 plane ----------------
__global__ void k_x2(const float* __restrict__ b2, __nv_bfloat16* __restrict__ ahi) {
    int i = blockIdx.x * blockDim.x + threadIdx.x;       // over NB*NV*128 quads
    int og = i & 127;
    int bv = i >> 7;
    int v = bv & (NV - 1);
    int b = bv >> 11;
    float a0 = g_s3b[bv * 3 + 0], a1 = g_s3b[bv * 3 + 1], a2 = g_s3b[bv * 3 + 2];
    float4 w0 = ((const float4*)g_W12c)[0 * 128 + og];
    float4 w1 = ((const float4*)g_W12c)[1 * 128 + og];
    float4 w2 = ((const float4*)g_W12c)[2 * 128 + og];
    float4 it = ((const float4*)g_imgterm)[b * 128 + og];
    float4 bw = ((const float4*)g_b1W2)[og];
    float4 bb = ((const float4*)b2)[og];
    float s1v = g_s1[v], s2v = g_s2[v];
    float r[4];
    r[0] = fmaxf(0.f, a0 * w0.x + a1 * w1.x + a2 * w2.x + s2v * it.x + s1v * bw.x + bb.x);
    r[1] = fmaxf(0.f, a0 * w0.y + a1 * w1.y + a2 * w2.y + s2v * it.y + s1v * bw.y + bb.y);
    r[2] = fmaxf(0.f, a0 * w0.z + a1 * w1.z + a2 * w2.z + s2v * it.z + s1v * bw.z + bb.z);
    r[3] = fmaxf(0.f, a0 * w0.w + a1 * w1.w + a2 * w2.w + s2v * it.w + s1v * bw.w + bb.w);
    ushort4 hv;
    unsigned short* hp = &hv.x;
#pragma unroll
    for (int q = 0; q < 4; q++) {
        __nv_bfloat16 h = __float2bfloat16(r[q]);
        hp[q] = *(unsigned short*)&h;
    }
    ((ushort4*)ahi)[(size_t)bv * 128 + og] = hv;
}

// ---------------- mma.sync bf16 GEMM: C[65536,512](bf16) = A @ W34 ----------------
// A bf16 [M,512] row-major; B = W34^T bf16 [512,512] (rows=n, cols=k) -> .col
// CTA 128x128, 8 warps (warp tile 32x64), K-chunk 32, double-buffered cp.async.
// Stage 16 KB: A@0, B@8192. 2 stages = 32 KB dynamic smem.
__global__ void __launch_bounds__(256, 2) gemm_mma(
    const uint4* __restrict__ Ah, const uint4* __restrict__ Bh,
    __nv_bfloat16* __restrict__ C) {
    extern __shared__ char smem[];
    uint32_t sb = smem_to_u32(smem);
    int tid = threadIdx.x, lane = tid & 31, wid = tid >> 5;
    int wr = wid & 3, wc = wid >> 2;                 // warp row (m), warp col (n)
    int row0 = blockIdx.y << 7, col0 = blockIdx.x << 7;

    auto load_chunk = [&](int kc, int stage) {
        uint32_t st = sb + stage * 16384;
#pragma unroll
        for (int i = tid; i < 512; i += 256) {
            int r = i >> 2, c = i & 3;
            uint32_t soff = SWZ(r * 64 + c * 16);
            size_t ga = (size_t)(row0 + r) * 64 + kc * 4 + c;
            size_t gb = (size_t)(col0 + r) * 64 + kc * 4 + c;
            CP_ASYNC16(st + soff,        (const void*)(Ah + ga));
            CP_ASYNC16(st + 8192 + soff, (const void*)(Bh + gb));
        }
    };

    load_chunk(0, 0);
    CP_COMMIT;
    CP_WAIT0;
    __syncthreads();

    float acc[2][8][4];
#pragma unroll
    for (int mt = 0; mt < 2; mt++)
#pragma unroll
        for (int nt = 0; nt < 8; nt++)
#pragma unroll
            for (int q = 0; q < 4; q++) acc[mt][nt][q] = 0.f;

    for (int kc = 0; kc < 16; kc++) {
        if (kc < 15) { load_chunk(kc + 1, (kc + 1) & 1); CP_COMMIT; }
        uint32_t base = sb + (kc & 1) * 16384;
#pragma unroll
        for (int ks = 0; ks < 2; ks++) {
            uint32_t ah[2][4];
#pragma unroll
            for (int mt = 0; mt < 2; mt++) {
                int r = wr * 32 + mt * 16 + (lane & 15);
                uint32_t off = SWZ(r * 64 + ks * 32 + ((lane >> 4) << 4));
                LDM4(ah[mt], base + off);
            }
#pragma unroll
            for (int nt2 = 0; nt2 < 4; nt2++) {
                int nrow = wc * 64 + nt2 * 16 + (lane & 7) + ((lane >> 4) << 3);
                uint32_t off = SWZ(nrow * 64 + ks * 32 + (((lane >> 3) & 1) << 4));
                uint32_t bhf[4];
                LDM4(bhf, base + 8192 + off);
#pragma unroll
                for (int h = 0; h < 2; h++) {
                    uint32_t bh2[2] = { bhf[2 * h], bhf[2 * h + 1] };
                    int nt = 2 * nt2 + h;
#pragma unroll
                    for (int mt = 0; mt < 2; mt++)
                        MMA16816(acc[mt][nt], ah[mt], bh2);
                }
            }
        }
        if (kc < 15) CP_WAIT0;
        __syncthreads();
    }

    // epilogue: bf16 store; row = row0+wr*32+mt*16+lane/4 (+8), col = col0+wc*64+nt*8+2*(lane%4)
#pragma unroll
    for (int mt = 0; mt < 2; mt++) {
        int row = row0 + wr * 32 + mt * 16 + (lane >> 2);
#pragma unroll
        for (int nt = 0; nt < 8; nt++) {
            int col = col0 + wc * 64 + nt * 8 + ((lane & 3) << 1);
            *(__nv_bfloat162*)&C[(size_t)row * 512 + col] =
                __floats2bfloat162_rn(acc[mt][nt][0], acc[mt][nt][1]);
            *(__nv_bfloat162*)&C[(size_t)(row + 8) * 512 + col] =
                __floats2bfloat162_rn(acc[mt][nt][2], acc[mt][nt][3]);
        }
    }
}

// ---------------- aggregation, F=512, bf16 in/out (fp32 accum) ----------------
__global__ void k_agg512h(const __nv_bfloat16* __restrict__ in, __nv_bfloat16* __restrict__ out) {
    int v = blockIdx.x, b = blockIdx.y, t = threadIdx.x;   // t < 128, 4 bf16 each
    const uint2* inb = (const uint2*)(in + (size_t)b * NV * 512);
    float4 acc = make_float4(0.f, 0.f, 0.f, 0.f);
    int beg = g_rowptr[v], end = g_rowptr[v + 1];
    for (int j = beg; j < end; j++) {
        int s = g_cols[j];
        float w = g_nrm[j];
        uint2 x = inb[(size_t)s * 128 + t];
        float2 f0 = __bfloat1622float2(*(__nv_bfloat162*)&x.x);
        float2 f1 = __bfloat1622float2(*(__nv_bfloat162*)&x.y);
        acc.x = fmaf(w, f0.x, acc.x);
        acc.y = fmaf(w, f0.y, acc.y);
        acc.z = fmaf(w, f1.x, acc.z);
        acc.w = fmaf(w, f1.y, acc.w);
    }
    uint2 o;
    *(__nv_bfloat162*)&o.x = __floats2bfloat162_rn(acc.x, acc.y);
    *(__nv_bfloat162*)&o.y = __floats2bfloat162_rn(acc.z, acc.w);
    ((uint2*)(out + (size_t)b * NV * 512))[(size_t)v * 128 + t] = o;
}

// ---------------- second F=512 aggregation fused with bias+relu+W56 projection ----------------
__global__ void k_agg512h_w56(const __nv_bfloat16* __restrict__ in, const float* __restrict__ b4) {
    int v = blockIdx.x, b = blockIdx.y, t = threadIdx.x;   // t < 128
    const uint2* inb = (const uint2*)(in + (size_t)b * NV * 512);
    float4 acc = make_float4(0.f, 0.f, 0.f, 0.f);
    int beg = g_rowptr[v], end = g_rowptr[v + 1];
    for (int j = beg; j < end; j++) {
        int s = g_cols[j];
        float w = g_nrm[j];
        uint2 x = inb[(size_t)s * 128 + t];
        float2 f0 = __bfloat1622float2(*(__nv_bfloat162*)&x.x);
        float2 f1 = __bfloat1622float2(*(__nv_bfloat162*)&x.y);
        acc.x = fmaf(w, f0.x, acc.x);
        acc.y = fmaf(w, f0.y, acc.y);
        acc.z = fmaf(w, f1.x, acc.z);
        acc.w = fmaf(w, f1.y, acc.w);
    }
    float s1v = g_s1[v];
    float4 ba = ((const float4*)g_b3W4)[t];
    float4 bb = ((const float4*)b4)[t];
    acc.x = fmaxf(0.f, acc.x + s1v * ba.x + bb.x);
    acc.y = fmaxf(0.f, acc.y + s1v * ba.y + bb.y);
    acc.z = fmaxf(0.f, acc.z + s1v * ba.z + bb.z);
    acc.w = fmaxf(0.f, acc.w + s1v * ba.w + bb.w);
    float p0 = acc.x * g_W56[(4 * t + 0) * 3 + 0] + acc.y * g_W56[(4 * t + 1) * 3 + 0]
             + acc.z * g_W56[(4 * t + 2) * 3 + 0] + acc.w * g_W56[(4 * t + 3) * 3 + 0];
    float p1 = acc.x * g_W56[(4 * t + 0) * 3 + 1] + acc.y * g_W56[(4 * t + 1) * 3 + 1]
             + acc.z * g_W56[(4 * t + 2) * 3 + 1] + acc.w * g_W56[(4 * t + 3) * 3 + 1];
    float p2 = acc.x * g_W56[(4 * t + 0) * 3 + 2] + acc.y * g_W56[(4 * t + 1) * 3 + 2]
             + acc.z * g_W56[(4 * t + 2) * 3 + 2] + acc.w * g_W56[(4 * t + 3) * 3 + 2];
#pragma unroll
    for (int off = 16; off; off >>= 1) {
        p0 += __shfl_down_sync(0xffffffffu, p0, off);
        p1 += __shfl_down_sync(0xffffffffu, p1, off);
        p2 += __shfl_down_sync(0xffffffffu, p2, off);
    }
    __shared__ float red[4][3];
    if ((t & 31) == 0) {
        red[t >> 5][0] = p0; red[t >> 5][1] = p1; red[t >> 5][2] = p2;
    }
    __syncthreads();
    if (t == 0) {
        float* o = g_s3a + ((size_t)b * NV + v) * 3;
        o[0] = red[0][0] + red[1][0] + red[2][0] + red[3][0];
        o[1] = red[0][1] + red[1][1] + red[2][1] + red[3][1];
        o[2] = red[0][2] + red[1][2] + red[2][2] + red[3][2];
    }
}

// ---------------- aggregation, F=3 ----------------
__global__ void k_agg3(const float* __restrict__ in, float* __restrict__ out,
                       const float* __restrict__ biasA, const float* __restrict__ biasB,
                       int relu) {
    int i = blockIdx.x * blockDim.x + threadIdx.x;
    if (i >= NB * NV) return;
    int v = i & (NV - 1);
    int b = i >> 11;
    float a0 = 0.f, a1 = 0.f, a2 = 0.f;
    int beg = g_rowptr[v], end = g_rowptr[v + 1];
    const float* base = in + (size_t)b * NV * 3;
    for (int j = beg; j < end; j++) {
        int s = g_cols[j];
        float w = g_nrm[j];
        const float* p = base + s * 3;
        a0 = fmaf(w, p[0], a0);
        a1 = fmaf(w, p[1], a1);
        a2 = fmaf(w, p[2], a2);
    }
    if (biasA) {
        float s1v = g_s1[v];
        a0 += s1v * biasA[0] + biasB[0];
        a1 += s1v * biasA[1] + biasB[1];
        a2 += s1v * biasA[2] + biasB[2];
    }
    if (relu) { a0 = fmaxf(0.f, a0); a1 = fmaxf(0.f, a1); a2 = fmaxf(0.f, a2); }
    float* o = out + (size_t)i * 3;
    o[0] = a0; o[1] = a1; o[2] = a2;
}

// ---------------- FC head: bias init + split-K GEMM with atomics ----------------
__global__ void k_cinit(const float* __restrict__ bias, float* __restrict__ C, int N) {
    int i = blockIdx.x * blockDim.x + threadIdx.x;
    if (i < 32 * N) C[i] = bias[i % N];
}

__global__ void __launch_bounds__(256) fcgemm_sk(const float* __restrict__ A,
                                                 const float* __restrict__ W,
                                                 float* __restrict__ C,
                                                 int K, int N, int Kc) {
    __shared__ float As[32][33];
    int tid = threadIdx.x;
    int o = blockIdx.x * 64 + (tid & 63);
    int bg = (tid >> 6) * 8;
    int k0base = blockIdx.y * Kc;
    float acc[8];
#pragma unroll
    for (int r = 0; r < 8; r++) acc[r] = 0.f;
    for (int k0 = k0base; k0 < k0base + Kc; k0 += 32) {
#pragma unroll
        for (int l = 0; l < 4; l++) {
            int idx = tid + 256 * l;
            int r = idx >> 5, kk = idx & 31;
            As[r][kk] = A[(size_t)r * K + k0 + kk];
        }
        __syncthreads();
#pragma unroll 8
        for (int kk = 0; kk < 32; kk++) {
            float w = W[(size_t)(k0 + kk) * N + o];
#pragma unroll
            for (int r = 0; r < 8; r++) acc[r] = fmaf(As[bg + r][kk], w, acc[r]);
        }
        __syncthreads();
    }
#pragma unroll
    for (int r = 0; r < 8; r++) atomicAdd(&C[(size_t)(bg + r) * N + o], acc[r]);
}

// ---------------- final: out = verts + 0.1*tanh(fcout) ----------------
__global__ void k_final(const float* __restrict__ verts, float* __restrict__ out) {
    int i = blockIdx.x * blockDim.x + threadIdx.x;
    if (i >= NB * NV * 3) return;
    out[i] = verts[i] + 0.1f * tanhf(g_fcout[i]);
}

// ---------------- host launcher ----------------
extern "C" void kernel_launch(void* const* d_in, const int* in_sizes, int n_in,
                              void* d_out, int out_size) {
    const float* verts = (const float*)d_in[0];
    const float* img   = (const float*)d_in[1];
    const int*   edge  = (const int*)d_in[2];
    const float* W1 = (const float*)d_in[3];   const float* b1 = (const float*)d_in[4];
    const float* W2 = (const float*)d_in[5];   const float* b2 = (const float*)d_in[6];
    const float* W3 = (const float*)d_in[7];   const float* b3 = (const float*)d_in[8];
    const float* W4 = (const float*)d_in[9];   const float* b4 = (const float*)d_in[10];
    const float* W5 = (const float*)d_in[11];  const float* b5 = (const float*)d_in[12];
    const float* W6 = (const float*)d_in[13];  const float* b6 = (const float*)d_in[14];
    const float* fcW1 = (const float*)d_in[15]; const float* fcb1 = (const float*)d_in[16];
    const float* fcW2 = (const float*)d_in[17]; const float* fcb2 = (const float*)d_in[18];
    const float* fcW3 = (const float*)d_in[19]; const float* fcb3 = (const float*)d_in[20];
    float* out = (float*)d_out;

    float *bufA, *bufB, *s3a, *s3b, *s3c, *imgstage, *imgterm;
    float *W34, *W12c, *W56, *b1W2, *b3W4, *b5W6, *fch1, *fch2, *fcout;
    __nv_bfloat16 *w34t;
    cudaGetSymbolAddress((void**)&bufA, g_bufA);
    cudaGetSymbolAddress((void**)&bufB, g_bufB);
    cudaGetSymbolAddress((void**)&s3a, g_s3a);
    cudaGetSymbolAddress((void**)&s3b, g_s3b);
    cudaGetSymbolAddress((void**)&s3c, g_s3c);
    cudaGetSymbolAddress((void**)&imgstage, g_imgstage);
    cudaGetSymbolAddress((void**)&imgterm, g_imgterm);
    cudaGetSymbolAddress((void**)&W34, g_W34);
    cudaGetSymbolAddress((void**)&w34t, g_W34T);
    cudaGetSymbolAddress((void**)&W12c, g_W12c);
    cudaGetSymbolAddress((void**)&W56, g_W56);
    cudaGetSymbolAddress((void**)&b1W2, g_b1W2);
    cudaGetSymbolAddress((void**)&b3W4, g_b3W4);
    cudaGetSymbolAddress((void**)&b5W6, g_b5W6);
    cudaGetSymbolAddress((void**)&fch1, g_fch1);
    cudaGetSymbolAddress((void**)&fch2, g_fch2);
    cudaGetSymbolAddress((void**)&fcout, g_fcout);

    // bf16 views: x2 plane in bufA, GEMM out in bufB, agg1 out back in bufA
    __nv_bfloat16* x2h  = (__nv_bfloat16*)bufA;
    __nv_bfloat16* yh   = (__nv_bfloat16*)bufB;
    __nv_bfloat16* agg1 = (__nv_bfloat16*)bufA + (size_t)NB * NV * 512;  // second half of bufA

    cudaFuncSetAttribute(gemm_mma, cudaFuncAttributeMaxDynamicSharedMemorySize, 32768);

    // --- graph/CSR + norm ---
    k_init<<<8, 256>>>();
    k_deg<<<48, 256>>>(edge);
    k_scan<<<1, 1024>>>();
    k_fill<<<56, 256>>>(edge);
    k_s1<<<8, 256>>>();
    k_s2<<<8, 256>>>();

    // --- fused weight precompute ---
    k_smallmm<<<6, 256>>>(W1, W2, W12c, 3, 512, 512, 512);
    k_smallmm<<<2, 256>>>(b1, W2, b1W2, 1, 512, 512, 512);
    k_smallmm<<<64, 256>>>(img, W1 + 3 * 512, imgstage, NB, 512, 512, 512);
    k_smallmm<<<64, 256>>>(imgstage, W2, imgterm, NB, 512, 512, 512);
    sgemm64<<<dim3(8, 8), 256>>>(W3, W4, W34, 512, 512, 512);
    k_splitT<<<1024, 256>>>();
    k_smallmm<<<2, 256>>>(b3, W4, b3W4, 1, 512, 512, 512);
    k_smallmm<<<6, 256>>>(W5, W6, W56, 512, 64, 3, 64);
    k_smallmm<<<1, 256>>>(b5, W6, b5W6, 1, 64, 3, 64);

    // --- layers 1+2 fused ---
    k_agg3<<<256, 256>>>(verts, s3a, NULL, NULL, 0);
    k_agg3<<<256, 256>>>(s3a, s3b, NULL, NULL, 0);
    k_x2<<<32768, 256>>>(b2, x2h);

    // --- layers 3+4 fused: y = x2 @ W34 (bf16 HMMA), then A^2 + bias + relu (+W56 proj) ---
    gemm_mma<<<dim3(4, 512), 256, 32768>>>((const uint4*)x2h, (const uint4*)w34t, yh);
    k_agg512h<<<dim3(NV, NB), 128>>>(yh, agg1);
    k_agg512h_w56<<<dim3(NV, NB), 128>>>(agg1, b4);    // -> s3a (projected by W56)

    // --- layers 5+6 remainder: A^2 on F=3 + bias + relu ---
    k_agg3<<<256, 256>>>(s3a, s3b, NULL, NULL, 0);
    k_agg3<<<256, 256>>>(s3b, s3c, b5W6, b6, 1);       // -> s3c ([32, 6144])

    // --- FC head (split-K + atomics) ---
    k_cinit<<<128, 256>>>(fcb1, fch1, 1024);
    fcgemm_sk<<<dim3(16, 8), 256>>>(s3c, fcW1, fch1, 6144, 1024, 768);
    k_cinit<<<128, 256>>>(fcb2, fch2, 1024);
    fcgemm_sk<<<dim3(16, 4), 256>>>(fch1, fcW2, fch2, 1024, 1024, 256);
    k_cinit<<<768, 256>>>(fcb3, fcout, 6144);
    fcgemm_sk<<<dim3(96, 2), 256>>>(fch2, fcW3, fcout, 1024, 6144, 512);

    // --- output ---
    k_final<<<768, 256>>>(verts, out);
}

// round 8
// speedup vs baseline: 5.2618x; 1.5145x over previous
#include <cuda_runtime.h>
#include <cuda_bf16.h>
#include <cstdint>
#include <math.h>

#define NB 32
#define NV 2048
#define NEDGE 12288
#define NNZ (NEDGE + NV)   // 14336 (edges + self loops)

// ================= helpers (plain sm_103-safe) =================
__device__ __forceinline__ uint32_t smem_to_u32(const void* smem_ptr) {
    uint32_t addr;
    asm("{ .reg .u64 tmp; cvta.to.shared.u64 tmp, %1; cvt.u32.u64 %0, tmp; }"
        : "=r"(addr) : "l"(smem_ptr));
    return addr;
}
#define SWZ(o) ((o) ^ (((o) >> 3) & 0x70))
#define CP_ASYNC16(dst, src) \
    asm volatile("cp.async.cg.shared.global [%0], [%1], 16;" :: "r"(dst), "l"(src))
#define CP_COMMIT asm volatile("cp.async.commit_group;" ::: "memory")
#define CP_WAIT_GROUP(n) asm volatile("cp.async.wait_group %0;" :: "n"(n) : "memory")
#define LDM4(r, addr) \
    asm volatile("ldmatrix.sync.aligned.m8n8.x4.shared.b16 {%0,%1,%2,%3}, [%4];" \
        : "=r"((r)[0]), "=r"((r)[1]), "=r"((r)[2]), "=r"((r)[3]) : "r"(addr))
#define MMA16816(d, a, b) \
    asm volatile("mma.sync.aligned.m16n8k16.row.col.f32.bf16.bf16.f32 " \
        "{%0,%1,%2,%3}, {%4,%5,%6,%7}, {%8,%9}, {%0,%1,%2,%3};" \
        : "+f"((d)[0]), "+f"((d)[1]), "+f"((d)[2]), "+f"((d)[3]) \
        : "r"((a)[0]), "r"((a)[1]), "r"((a)[2]), "r"((a)[3]), "r"((b)[0]), "r"((b)[1]))

// ---------------- scratch (device globals; no allocation) ----------------
__device__ float g_bufA[(size_t)NB * NV * 512];   // x2 bf16 plane (half 0), agg1 bf16 (half 1)
__device__ float g_bufB[(size_t)NB * NV * 512];   // y = x2@W34 bf16
__device__ float g_s3a[NB * NV * 3];
__device__ float g_s3b[NB * NV * 3];
__device__ float g_s3c[NB * NV * 3];
__device__ float g_imgstage[NB * 512];
__device__ float g_imgterm[NB * 512];
__device__ __nv_bfloat16 g_W34T[512 * 512];       // W34 transposed [N,K] bf16
__device__ float g_W12c[3 * 512];
__device__ float g_W56[512 * 3];
__device__ float g_b1W2[512];
__device__ float g_b3W4[512];
__device__ float g_b5W6[3];
__device__ float g_s1[NV];
__device__ float g_s2[NV];
__device__ float g_dinv[NV];
__device__ float g_nrm[NNZ];
__device__ int   g_rowptr[NV + 1];
__device__ int   g_cols[NNZ];
__device__ int   g_counts[NV];
__device__ int   g_fill[NV];
__device__ float g_fch1[NB * 1024];
__device__ float g_fch2[NB * 1024];
__device__ float g_fcout[NB * 6144];

// ---------------- graph/CSR setup ----------------
__global__ void k_init() {
    int i = blockIdx.x * blockDim.x + threadIdx.x;
    if (i < NV) { g_counts[i] = 1; g_fill[i] = 0; }
}
__global__ void k_deg(const int* __restrict__ edge) {
    int e = blockIdx.x * blockDim.x + threadIdx.x;
    if (e < NEDGE) atomicAdd(&g_counts[edge[NEDGE + e]], 1);
}
__global__ void k_scan() {
    __shared__ int p[1024];
    int t = threadIdx.x;
    int c0 = g_counts[2 * t], c1 = g_counts[2 * t + 1];
    g_dinv[2 * t]     = rsqrtf((float)c0);
    g_dinv[2 * t + 1] = rsqrtf((float)c1);
    p[t] = c0 + c1;
    __syncthreads();
    for (int off = 1; off < 1024; off <<= 1) {
        int v = (t >= off) ? p[t - off] : 0;
        __syncthreads();
        p[t] += v;
        __syncthreads();
    }
    int base = p[t] - (c0 + c1);
    g_rowptr[2 * t] = base;
    g_rowptr[2 * t + 1] = base + c0;
    if (t == 1023) g_rowptr[2048] = p[1023];
}
__global__ void k_fill(const int* __restrict__ edge) {
    int i = blockIdx.x * blockDim.x + threadIdx.x;
    if (i < NEDGE) {
        int s = edge[i], d = edge[NEDGE + i];
        int pos = g_rowptr[d] + atomicAdd(&g_fill[d], 1);
        g_cols[pos] = s;
        g_nrm[pos] = g_dinv[s] * g_dinv[d];
    } else if (i < NNZ) {
        int v = i - NEDGE;
        int pos = g_rowptr[v] + atomicAdd(&g_fill[v], 1);
        g_cols[pos] = v;
        g_nrm[pos] = g_dinv[v] * g_dinv[v];
    }
}
__global__ void k_s1() {
    int v = blockIdx.x * blockDim.x + threadIdx.x;
    if (v >= NV) return;
    float s = 0.f;
    for (int j = g_rowptr[v]; j < g_rowptr[v + 1]; j++) s += g_nrm[j];
    g_s1[v] = s;
}
__global__ void k_s2() {
    int v = blockIdx.x * blockDim.x + threadIdx.x;
    if (v >= NV) return;
    float s = 0.f;
    for (int j = g_rowptr[v]; j < g_rowptr[v + 1]; j++) s += g_nrm[j] * g_s1[g_cols[j]];
    g_s2[v] = s;
}

// ---------------- generic small matmul (imgstage/imgterm) ----------------
__global__ void k_smallmm(const float* __restrict__ A, const float* __restrict__ Bw,
                          float* __restrict__ C, int M, int K, int N, int strideA) {
    int i = blockIdx.x * blockDim.x + threadIdx.x;
    if (i >= M * N) return;
    int m = i / N, o = i - m * N;
    float acc = 0.f;
    const float* a = A + (size_t)m * strideA;
    for (int k = 0; k < K; k++) acc += a[k] * Bw[(size_t)k * N + o];
    C[i] = acc;
}

// ---------------- fused tiny weight-prep (W12c, b1W2, b3W4, W56, b5W6) ----------------
__global__ void k_prepsmall(const float* __restrict__ W1, const float* __restrict__ W2,
                            const float* __restrict__ b1, const float* __restrict__ b3,
                            const float* __restrict__ W4, const float* __restrict__ W5,
                            const float* __restrict__ W6, const float* __restrict__ b5) {
    int i = blockIdx.x * blockDim.x + threadIdx.x;
    if (i < 1536) {                       // W12c = W1[0:3] @ W2
        int m = i / 512, o = i - m * 512;
        float acc = 0.f;
        for (int k = 0; k < 512; k++) acc += W1[m * 512 + k] * W2[(size_t)k * 512 + o];
        g_W12c[i] = acc;
    } else if (i < 2048) {                // b1W2 = b1 @ W2
        int o = i - 1536;
        float acc = 0.f;
        for (int k = 0; k < 512; k++) acc += b1[k] * W2[(size_t)k * 512 + o];
        g_b1W2[o] = acc;
    } else if (i < 2560) {                // b3W4 = b3 @ W4
        int o = i - 2048;
        float acc = 0.f;
        for (int k = 0; k < 512; k++) acc += b3[k] * W4[(size_t)k * 512 + o];
        g_b3W4[o] = acc;
    } else if (i < 4096) {                // W56 = W5 @ W6
        int j = i - 2560;
        int m = j / 3, o = j - m * 3;
        float acc = 0.f;
        for (int k = 0; k < 64; k++) acc += W5[m * 64 + k] * W6[k * 3 + o];
        g_W56[j] = acc;
    } else if (i < 4099) {                // b5W6 = b5 @ W6
        int o = i - 4096;
        float acc = 0.f;
        for (int k = 0; k < 64; k++) acc += b5[k] * W6[k * 3 + o];
        g_b5W6[o] = acc;
    }
}

// ---------------- W34 = W3@W4, epilogue writes transposed bf16 directly ----------------
__global__ void __launch_bounds__(256) sgemm64T(const float* __restrict__ A,
                                                const float* __restrict__ Bw,
                                                int M, int N, int K) {
    __shared__ float As[16][64];
    __shared__ float Bs[16][68];
    int tid = threadIdx.x;
    int row0 = blockIdx.y * 64, col0 = blockIdx.x * 64;
    int aRow = tid >> 2, aCol = (tid & 3) * 4;
    int bRow = tid >> 4, bCol = (tid & 15) * 4;
    int tx = tid & 15, ty = tid >> 4;
    float acc[4][4];
#pragma unroll
    for (int i = 0; i < 4; i++)
#pragma unroll
        for (int j = 0; j < 4; j++) acc[i][j] = 0.f;
    for (int k0 = 0; k0 < K; k0 += 16) {
        float4 av = *(const float4*)&A[(size_t)(row0 + aRow) * K + k0 + aCol];
        float4 bv = *(const float4*)&Bw[(size_t)(k0 + bRow) * N + col0 + bCol];
        As[aCol + 0][aRow] = av.x;
        As[aCol + 1][aRow] = av.y;
        As[aCol + 2][aRow] = av.z;
        As[aCol + 3][aRow] = av.w;
        Bs[bRow][bCol + 0] = bv.x;
        Bs[bRow][bCol + 1] = bv.y;
        Bs[bRow][bCol + 2] = bv.z;
        Bs[bRow][bCol + 3] = bv.w;
        __syncthreads();
#pragma unroll
        for (int kk = 0; kk < 16; kk++) {
            float ar[4], br[4];
#pragma unroll
            for (int i = 0; i < 4; i++) ar[i] = As[kk][ty * 4 + i];
#pragma unroll
            for (int j = 0; j < 4; j++) br[j] = Bs[kk][tx * 4 + j];
#pragma unroll
            for (int i = 0; i < 4; i++)
#pragma unroll
                for (int j = 0; j < 4; j++) acc[i][j] = fmaf(ar[i], br[j], acc[i][j]);
        }
        __syncthreads();
    }
    // write transposed bf16: W34T[n, k] = W34[k, n]; k = row (m-index), n = col
#pragma unroll
    for (int i = 0; i < 4; i++) {
        int krow = row0 + ty * 4 + i;
#pragma unroll
        for (int j = 0; j < 4; j++) {
            int ncol = col0 + tx * 4 + j;
            g_W34T[(size_t)ncol * 512 + krow] = __float2bfloat16(acc[i][j]);
        }
    }
}

// ---------------- x2 assembly -> bf16 plane ----------------
__global__ void k_x2(const float* __restrict__ b2, __nv_bfloat16* __restrict__ ahi) {
    int i = blockIdx.x * blockDim.x + threadIdx.x;       // over NB*NV*128 quads
    int og = i & 127;
    int bv = i >> 7;
    int v = bv & (NV - 1);
    int b = bv >> 11;
    float a0 = g_s3b[bv * 3 + 0], a1 = g_s3b[bv * 3 + 1], a2 = g_s3b[bv * 3 + 2];
    float4 w0 = ((const float4*)g_W12c)[0 * 128 + og];
    float4 w1 = ((const float4*)g_W12c)[1 * 128 + og];
    float4 w2 = ((const float4*)g_W12c)[2 * 128 + og];
    float4 it = ((const float4*)g_imgterm)[b * 128 + og];
    float4 bw = ((const float4*)g_b1W2)[og];
    float4 bb = ((const float4*)b2)[og];
    float s1v = g_s1[v], s2v = g_s2[v];
    float r[4];
    r[0] = fmaxf(0.f, a0 * w0.x + a1 * w1.x + a2 * w2.x + s2v * it.x + s1v * bw.x + bb.x);
    r[1] = fmaxf(0.f, a0 * w0.y + a1 * w1.y + a2 * w2.y + s2v * it.y + s1v * bw.y + bb.y);
    r[2] = fmaxf(0.f, a0 * w0.z + a1 * w1.z + a2 * w2.z + s2v * it.z + s1v * bw.z + bb.z);
    r[3] = fmaxf(0.f, a0 * w0.w + a1 * w1.w + a2 * w2.w + s2v * it.w + s1v * bw.w + bb.w);
    ushort4 hv;
    unsigned short* hp = &hv.x;
#pragma unroll
    for (int q = 0; q < 4; q++) {
        __nv_bfloat16 h = __float2bfloat16(r[q]);
        hp[q] = *(unsigned short*)&h;
    }
    ((ushort4*)ahi)[(size_t)bv * 128 + og] = hv;
}

// ---------------- mma.sync bf16 GEMM: C[65536,512](bf16) = A @ W34 ----------------
// 4-stage cp.async pipeline, stage 16 KB (A 8K + B 8K), 64 KB dynamic smem.
__global__ void __launch_bounds__(256, 2) gemm_mma(
    const uint4* __restrict__ Ah, const uint4* __restrict__ Bh,
    __nv_bfloat16* __restrict__ C) {
    extern __shared__ char smem[];
    uint32_t sb = smem_to_u32(smem);
    int tid = threadIdx.x, lane = tid & 31, wid = tid >> 5;
    int wr = wid & 3, wc = wid >> 2;                 // warp row (m), warp col (n)
    int row0 = blockIdx.y << 7, col0 = blockIdx.x << 7;

    auto load_chunk = [&](int kc, int stage) {
        uint32_t st = sb + stage * 16384;
#pragma unroll
        for (int i = tid; i < 512; i += 256) {
            int r = i >> 2, c = i & 3;
            uint32_t soff = SWZ(r * 64 + c * 16);
            size_t ga = (size_t)(row0 + r) * 64 + kc * 4 + c;
            size_t gb = (size_t)(col0 + r) * 64 + kc * 4 + c;
            CP_ASYNC16(st + soff,        (const void*)(Ah + ga));
            CP_ASYNC16(st + 8192 + soff, (const void*)(Bh + gb));
        }
    };

    load_chunk(0, 0); CP_COMMIT;
    load_chunk(1, 1); CP_COMMIT;
    load_chunk(2, 2); CP_COMMIT;

    float acc[2][8][4];
#pragma unroll
    for (int mt = 0; mt < 2; mt++)
#pragma unroll
        for (int nt = 0; nt < 8; nt++)
#pragma unroll
            for (int q = 0; q < 4; q++) acc[mt][nt][q] = 0.f;

    for (int kc = 0; kc < 16; kc++) {
        CP_WAIT_GROUP(2);          // stage kc resident
        __syncthreads();           // all warps done with stage (kc-1)&3, data visible
        if (kc + 3 < 16) load_chunk(kc + 3, (kc + 3) & 3);
        CP_COMMIT;                 // commit every iter (empty group ok) to keep accounting
        uint32_t base = sb + (kc & 3) * 16384;
#pragma unroll
        for (int ks = 0; ks < 2; ks++) {
            uint32_t ah[2][4];
#pragma unroll
            for (int mt = 0; mt < 2; mt++) {
                int r = wr * 32 + mt * 16 + (lane & 15);
                uint32_t off = SWZ(r * 64 + ks * 32 + ((lane >> 4) << 4));
                LDM4(ah[mt], base + off);
            }
#pragma unroll
            for (int nt2 = 0; nt2 < 4; nt2++) {
                int nrow = wc * 64 + nt2 * 16 + (lane & 7) + ((lane >> 4) << 3);
                uint32_t off = SWZ(nrow * 64 + ks * 32 + (((lane >> 3) & 1) << 4));
                uint32_t bhf[4];
                LDM4(bhf, base + 8192 + off);
#pragma unroll
                for (int h = 0; h < 2; h++) {
                    uint32_t bh2[2] = { bhf[2 * h], bhf[2 * h + 1] };
                    int nt = 2 * nt2 + h;
#pragma unroll
                    for (int mt = 0; mt < 2; mt++)
                        MMA16816(acc[mt][nt], ah[mt], bh2);
                }
            }
        }
    }

    // epilogue: bf16 store
#pragma unroll
    for (int mt = 0; mt < 2; mt++) {
        int row = row0 + wr * 32 + mt * 16 + (lane >> 2);
#pragma unroll
        for (int nt = 0; nt < 8; nt++) {
            int col = col0 + wc * 64 + nt * 8 + ((lane & 3) << 1);
            *(__nv_bfloat162*)&C[(size_t)row * 512 + col] =
                __floats2bfloat162_rn(acc[mt][nt][0], acc[mt][nt][1]);
            *(__nv_bfloat162*)&C[(size_t)(row + 8) * 512 + col] =
                __floats2bfloat162_rn(acc[mt][nt][2], acc[mt][nt][3]);
        }
    }
}

// ---------------- aggregation, F=512, bf16 in/out (fp32 accum) ----------------
__global__ void k_agg512h(const __nv_bfloat16* __restrict__ in, __nv_bfloat16* __restrict__ out) {
    int v = blockIdx.x, b = blockIdx.y, t = threadIdx.x;   // t < 128, 4 bf16 each
    const uint2* inb = (const uint2*)(in + (size_t)b * NV * 512);
    float4 acc = make_float4(0.f, 0.f, 0.f, 0.f);
    int beg = g_rowptr[v], end = g_rowptr[v + 1];
    for (int j = beg; j < end; j++) {
        int s = g_cols[j];
        float w = g_nrm[j];
        uint2 x = inb[(size_t)s * 128 + t];
        float2 f0 = __bfloat1622float2(*(__nv_bfloat162*)&x.x);
        float2 f1 = __bfloat1622float2(*(__nv_bfloat162*)&x.y);
        acc.x = fmaf(w, f0.x, acc.x);
        acc.y = fmaf(w, f0.y, acc.y);
        acc.z = fmaf(w, f1.x, acc.z);
        acc.w = fmaf(w, f1.y, acc.w);
    }
    uint2 o;
    *(__nv_bfloat162*)&o.x = __floats2bfloat162_rn(acc.x, acc.y);
    *(__nv_bfloat162*)&o.y = __floats2bfloat162_rn(acc.z, acc.w);
    ((uint2*)(out + (size_t)b * NV * 512))[(size_t)v * 128 + t] = o;
}

// ---------------- second F=512 aggregation fused with bias+relu+W56 projection ----------------
__global__ void k_agg512h_w56(const __nv_bfloat16* __restrict__ in, const float* __restrict__ b4) {
    int v = blockIdx.x, b = blockIdx.y, t = threadIdx.x;   // t < 128
    const uint2* inb = (const uint2*)(in + (size_t)b * NV * 512);
    float4 acc = make_float4(0.f, 0.f, 0.f, 0.f);
    int beg = g_rowptr[v], end = g_rowptr[v + 1];
    for (int j = beg; j < end; j++) {
        int s = g_cols[j];
        float w = g_nrm[j];
        uint2 x = inb[(size_t)s * 128 + t];
        float2 f0 = __bfloat1622float2(*(__nv_bfloat162*)&x.x);
        float2 f1 = __bfloat1622float2(*(__nv_bfloat162*)&x.y);
        acc.x = fmaf(w, f0.x, acc.x);
        acc.y = fmaf(w, f0.y, acc.y);
        acc.z = fmaf(w, f1.x, acc.z);
        acc.w = fmaf(w, f1.y, acc.w);
    }
    float s1v = g_s1[v];
    float4 ba = ((const float4*)g_b3W4)[t];
    float4 bb = ((const float4*)b4)[t];
    acc.x = fmaxf(0.f, acc.x + s1v * ba.x + bb.x);
    acc.y = fmaxf(0.f, acc.y + s1v * ba.y + bb.y);
    acc.z = fmaxf(0.f, acc.z + s1v * ba.z + bb.z);
    acc.w = fmaxf(0.f, acc.w + s1v * ba.w + bb.w);
    float p0 = acc.x * g_W56[(4 * t + 0) * 3 + 0] + acc.y * g_W56[(4 * t + 1) * 3 + 0]
             + acc.z * g_W56[(4 * t + 2) * 3 + 0] + acc.w * g_W56[(4 * t + 3) * 3 + 0];
    float p1 = acc.x * g_W56[(4 * t + 0) * 3 + 1] + acc.y * g_W56[(4 * t + 1) * 3 + 1]
             + acc.z * g_W56[(4 * t + 2) * 3 + 1] + acc.w * g_W56[(4 * t + 3) * 3 + 1];
    float p2 = acc.x * g_W56[(4 * t + 0) * 3 + 2] + acc.y * g_W56[(4 * t + 1) * 3 + 2]
             + acc.z * g_W56[(4 * t + 2) * 3 + 2] + acc.w * g_W56[(4 * t + 3) * 3 + 2];
#pragma unroll
    for (int off = 16; off; off >>= 1) {
        p0 += __shfl_down_sync(0xffffffffu, p0, off);
        p1 += __shfl_down_sync(0xffffffffu, p1, off);
        p2 += __shfl_down_sync(0xffffffffu, p2, off);
    }
    __shared__ float red[4][3];
    if ((t & 31) == 0) {
        red[t >> 5][0] = p0; red[t >> 5][1] = p1; red[t >> 5][2] = p2;
    }
    __syncthreads();
    if (t == 0) {
        float* o = g_s3a + ((size_t)b * NV + v) * 3;
        o[0] = red[0][0] + red[1][0] + red[2][0] + red[3][0];
        o[1] = red[0][1] + red[1][1] + red[2][1] + red[3][1];
        o[2] = red[0][2] + red[1][2] + red[2][2] + red[3][2];
    }
}

// ---------------- aggregation, F=3 ----------------
__global__ void k_agg3(const float* __restrict__ in, float* __restrict__ out,
                       const float* __restrict__ biasA, const float* __restrict__ biasB,
                       int relu) {
    int i = blockIdx.x * blockDim.x + threadIdx.x;
    if (i >= NB * NV) return;
    int v = i & (NV - 1);
    int b = i >> 11;
    float a0 = 0.f, a1 = 0.f, a2 = 0.f;
    int beg = g_rowptr[v], end = g_rowptr[v + 1];
    const float* base = in + (size_t)b * NV * 3;
    for (int j = beg; j < end; j++) {
        int s = g_cols[j];
        float w = g_nrm[j];
        const float* p = base + s * 3;
        a0 = fmaf(w, p[0], a0);
        a1 = fmaf(w, p[1], a1);
        a2 = fmaf(w, p[2], a2);
    }
    if (biasA) {
        float s1v = g_s1[v];
        a0 += s1v * biasA[0] + biasB[0];
        a1 += s1v * biasA[1] + biasB[1];
        a2 += s1v * biasA[2] + biasB[2];
    }
    if (relu) { a0 = fmaxf(0.f, a0); a1 = fmaxf(0.f, a1); a2 = fmaxf(0.f, a2); }
    float* o = out + (size_t)i * 3;
    o[0] = a0; o[1] = a1; o[2] = a2;
}

// ---------------- FC head: one fused bias init + split-K GEMMs with atomics ----------------
__global__ void k_cinit3(const float* __restrict__ fcb1, const float* __restrict__ fcb2,
                         const float* __restrict__ fcb3) {
    int i = blockIdx.x * blockDim.x + threadIdx.x;   // 32*6144 = 196608 threads
    if (i < 32 * 1024) {
        g_fch1[i] = fcb1[i & 1023];
        g_fch2[i] = fcb2[i & 1023];
    }
    if (i < 32 * 6144) g_fcout[i] = fcb3[i % 6144];
}

__global__ void __launch_bounds__(256) fcgemm_sk(const float* __restrict__ A,
                                                 const float* __restrict__ W,
                                                 float* __restrict__ C,
                                                 int K, int N, int Kc) {
    __shared__ float As[32][33];
    int tid = threadIdx.x;
    int o = blockIdx.x * 64 + (tid & 63);
    int bg = (tid >> 6) * 8;
    int k0base = blockIdx.y * Kc;
    float acc[8];
#pragma unroll
    for (int r = 0; r < 8; r++) acc[r] = 0.f;
    for (int k0 = k0base; k0 < k0base + Kc; k0 += 32) {
#pragma unroll
        for (int l = 0; l < 4; l++) {
            int idx = tid + 256 * l;
            int r = idx >> 5, kk = idx & 31;
            As[r][kk] = A[(size_t)r * K + k0 + kk];
        }
        __syncthreads();
#pragma unroll 8
        for (int kk = 0; kk < 32; kk++) {
            float w = W[(size_t)(k0 + kk) * N + o];
#pragma unroll
            for (int r = 0; r < 8; r++) acc[r] = fmaf(As[bg + r][kk], w, acc[r]);
        }
        __syncthreads();
    }
#pragma unroll
    for (int r = 0; r < 8; r++) atomicAdd(&C[(size_t)(bg + r) * N + o], acc[r]);
}

// ---------------- final: out = verts + 0.1*tanh(fcout) ----------------
__global__ void k_final(const float* __restrict__ verts, float* __restrict__ out) {
    int i = blockIdx.x * blockDim.x + threadIdx.x;
    if (i >= NB * NV * 3) return;
    out[i] = verts[i] + 0.1f * tanhf(g_fcout[i]);
}

// ---------------- host launcher ----------------
extern "C" void kernel_launch(void* const* d_in, const int* in_sizes, int n_in,
                              void* d_out, int out_size) {
    const float* verts = (const float*)d_in[0];
    const float* img   = (const float*)d_in[1];
    const int*   edge  = (const int*)d_in[2];
    const float* W1 = (const float*)d_in[3];   const float* b1 = (const float*)d_in[4];
    const float* W2 = (const float*)d_in[5];   const float* b2 = (const float*)d_in[6];
    const float* W3 = (const float*)d_in[7];   const float* b3 = (const float*)d_in[8];
    const float* W4 = (const float*)d_in[9];   const float* b4 = (const float*)d_in[10];
    const float* W5 = (const float*)d_in[11];  const float* b5 = (const float*)d_in[12];
    const float* W6 = (const float*)d_in[13];  const float* b6 = (const float*)d_in[14];
    const float* fcW1 = (const float*)d_in[15]; const float* fcb1 = (const float*)d_in[16];
    const float* fcW2 = (const float*)d_in[17]; const float* fcb2 = (const float*)d_in[18];
    const float* fcW3 = (const float*)d_in[19]; const float* fcb3 = (const float*)d_in[20];
    float* out = (float*)d_out;

    float *bufA, *bufB, *s3a, *s3b, *s3c, *imgstage, *imgterm, *b5W6;
    float *fch1, *fch2, *fcout;
    __nv_bfloat16 *w34t;
    cudaGetSymbolAddress((void**)&bufA, g_bufA);
    cudaGetSymbolAddress((void**)&bufB, g_bufB);
    cudaGetSymbolAddress((void**)&s3a, g_s3a);
    cudaGetSymbolAddress((void**)&s3b, g_s3b);
    cudaGetSymbolAddress((void**)&s3c, g_s3c);
    cudaGetSymbolAddress((void**)&imgstage, g_imgstage);
    cudaGetSymbolAddress((void**)&imgterm, g_imgterm);
    cudaGetSymbolAddress((void**)&w34t, g_W34T);
    cudaGetSymbolAddress((void**)&b5W6, g_b5W6);
    cudaGetSymbolAddress((void**)&fch1, g_fch1);
    cudaGetSymbolAddress((void**)&fch2, g_fch2);
    cudaGetSymbolAddress((void**)&fcout, g_fcout);

    // bf16 views: x2 plane in bufA (half 0), GEMM out in bufB, agg1 in bufA half 1
    __nv_bfloat16* x2h  = (__nv_bfloat16*)bufA;
    __nv_bfloat16* yh   = (__nv_bfloat16*)bufB;
    __nv_bfloat16* agg1 = (__nv_bfloat16*)bufA + (size_t)NB * NV * 512;

    cudaFuncSetAttribute(gemm_mma, cudaFuncAttributeMaxDynamicSharedMemorySize, 65536);

    // --- graph/CSR + norm ---
    k_init<<<8, 256>>>();
    k_deg<<<48, 256>>>(edge);
    k_scan<<<1, 1024>>>();
    k_fill<<<56, 256>>>(edge);
    k_s1<<<8, 256>>>();
    k_s2<<<8, 256>>>();

    // --- fused weight precompute ---
    k_prepsmall<<<17, 256>>>(W1, W2, b1, b3, W4, W5, W6, b5);
    k_smallmm<<<64, 256>>>(img, W1 + 3 * 512, imgstage, NB, 512, 512, 512);
    k_smallmm<<<64, 256>>>(imgstage, W2, imgterm, NB, 512, 512, 512);
    sgemm64T<<<dim3(8, 8), 256>>>(W3, W4, 512, 512, 512);   // -> g_W34T bf16

    // --- layers 1+2 fused ---
    k_agg3<<<256, 256>>>(verts, s3a, NULL, NULL, 0);
    k_agg3<<<256, 256>>>(s3a, s3b, NULL, NULL, 0);
    k_x2<<<32768, 256>>>(b2, x2h);

    // --- layers 3+4 fused: y = x2 @ W34 (bf16 HMMA, 4-stage pipe), then A^2 (+W56 proj) ---
    gemm_mma<<<dim3(4, 512), 256, 65536>>>((const uint4*)x2h, (const uint4*)w34t, yh);
    k_agg512h<<<dim3(NV, NB), 128>>>(yh, agg1);
    k_agg512h_w56<<<dim3(NV, NB), 128>>>(agg1, b4);    // -> s3a (projected by W56)

    // --- layers 5+6 remainder: A^2 on F=3 + bias + relu ---
    k_agg3<<<256, 256>>>(s3a, s3b, NULL, NULL, 0);
    k_agg3<<<256, 256>>>(s3b, s3c, b5W6, b6, 1);       // -> s3c ([32, 6144])

    // --- FC head (deep split-K + atomics) ---
    k_cinit3<<<768, 256>>>(fcb1, fcb2, fcb3);
    fcgemm_sk<<<dim3(16, 24), 256>>>(s3c, fcW1, fch1, 6144, 1024, 256);
    fcgemm_sk<<<dim3(16, 8), 256>>>(fch1, fcW2, fch2, 1024, 1024, 128);
    fcgemm_sk<<<dim3(96, 4), 256>>>(fch2, fcW3, fcout, 1024, 6144, 256);

    // --- output ---
    k_final<<<768, 256>>>(verts, out);
}